// round 2
// baseline (speedup 1.0000x reference)
#include <cuda_runtime.h>
#include <math.h>
#include <stdint.h>

#define BB 4
#define TT 1024
#define CC 2048
#define HH 32
#define NNd 64
#define KVD 512
#define MM (BB*TT)   // 4096 tokens

// ---------------- scratch (static device arrays; no allocation) ----------------
__device__ float g_hidden[MM*160];            // [th(64) | ha(64) | hv(32..160)]
__device__ float g_r[(size_t)MM*CC];
__device__ float g_kproj[(size_t)MM*KVD];
__device__ float g_vproj[(size_t)MM*KVD];
__device__ float g_wterm[(size_t)MM*CC];
__device__ float g_aterm[(size_t)MM*CC];
__device__ float g_vterm[(size_t)MM*CC];
__device__ float g_packed[(size_t)BB*HH*TT*384];  // per (b,h,t): r,decay,kmod,vb,aa,bb (6x64)
__device__ float g_y[(size_t)MM*CC];
__device__ float g_xx[(size_t)MM*CC];
__device__ float g_bcoef[(size_t)MM*HH];
__device__ float g_gn[BB*HH*2];               // mean, rstd per (b,h)
__device__ float g_WhT[160*CC];               // packed [w1^T; a1^T; v1^T] (160, 2048)
__device__ float g_w2T[CC*64];
__device__ float g_a2T[CC*64];
__device__ float g_v2T[CC*32];

// ---------------- helpers ----------------
__device__ __forceinline__ float sigmoidf_(float x){ return 1.0f/(1.0f + expf(-x)); }

__device__ __forceinline__ float redux16(float v){
    v += __shfl_xor_sync(0xffffffffu, v, 1);
    v += __shfl_xor_sync(0xffffffffu, v, 2);
    v += __shfl_xor_sync(0xffffffffu, v, 4);
    v += __shfl_xor_sync(0xffffffffu, v, 8);
    return v;
}

__device__ __forceinline__ void cp_async16(void* smem, const void* gmem){
    unsigned s = (unsigned)__cvta_generic_to_shared(smem);
    asm volatile("cp.async.cg.shared.global [%0], [%1], 16;\n" :: "r"(s), "l"(gmem));
}

// ---------------- weight packing (transposes) ----------------
__global__ void pack_weights(const float* __restrict__ w1, const float* __restrict__ a1,
                             const float* __restrict__ v1, const float* __restrict__ w2,
                             const float* __restrict__ a2, const float* __restrict__ v2)
{
    int stride = gridDim.x * blockDim.x;
    int idx0 = blockIdx.x * blockDim.x + threadIdx.x;
    // WhT (160, 2048)
    for (int i = idx0; i < 160*CC; i += stride) {
        int rowj = i / CC, c = i % CC;
        float v;
        if (rowj < 64)       v = w1[c*64 + rowj];
        else if (rowj < 128) v = a1[c*64 + (rowj-64)];
        else                 v = v1[c*32 + (rowj-128)];
        g_WhT[i] = v;
    }
    // w2T/a2T (2048,64), v2T (2048,32)
    for (int i = idx0; i < CC*64; i += stride) {
        int c = i / 64, r = i % 64;
        g_w2T[i] = w2[r*CC + c];
        g_a2T[i] = a2[r*CC + c];
    }
    for (int i = idx0; i < CC*32; i += stride) {
        int c = i / 32, r = i % 32;
        g_v2T[i] = v2[r*CC + c];
    }
}

__global__ void tanh_hidden(){
    int idx = blockIdx.x * blockDim.x + threadIdx.x;  // over MM*64
    if (idx < MM*64) {
        int m = idx >> 6, i = idx & 63;
        g_hidden[m*160 + i] = tanhf(g_hidden[m*160 + i]);
    }
}

// ---------------- generic fp32 NT SGEMM: C = A * B^T + bias ----------------
// A: (M,K) row-major lda; B: (N,K) row-major ldb; C: (M,ldc)
template<int BM,int BN,int BK,int TM,int TN>
__global__ void __launch_bounds__((BM/TM)*(BN/TN)) sgemm_nt(
        const float* __restrict__ A, int lda,
        const float* __restrict__ Bm, int ldb,
        const float* __restrict__ bias,
        float* __restrict__ C, int ldc,
        int M, int N, int K)
{
    constexpr int THREADS = (BM/TM)*(BN/TN);
    __shared__ float As[BK][BM];
    __shared__ float Bs[BK][BN];
    const int tid  = threadIdx.x;
    const int bm   = blockIdx.y * BM;
    const int bn   = blockIdx.x * BN;
    const int tcol = tid % (BN/TN);
    const int trow = tid / (BN/TN);

    float acc[TM][TN];
    #pragma unroll
    for (int i=0;i<TM;i++)
        #pragma unroll
        for (int j=0;j<TN;j++) acc[i][j]=0.f;

    for (int k0 = 0; k0 < K; k0 += BK) {
        for (int idx = tid; idx < BM*BK/4; idx += THREADS) {
            int row = idx / (BK/4), kq = idx % (BK/4);
            const float4 v = *(const float4*)(A + (size_t)(bm+row)*lda + k0 + kq*4);
            As[kq*4+0][row]=v.x; As[kq*4+1][row]=v.y; As[kq*4+2][row]=v.z; As[kq*4+3][row]=v.w;
        }
        for (int idx = tid; idx < BN*BK/4; idx += THREADS) {
            int row = idx / (BK/4), kq = idx % (BK/4);
            int n = bn + row;
            float4 v = make_float4(0.f,0.f,0.f,0.f);
            if (n < N) v = *(const float4*)(Bm + (size_t)n*ldb + k0 + kq*4);
            Bs[kq*4+0][row]=v.x; Bs[kq*4+1][row]=v.y; Bs[kq*4+2][row]=v.z; Bs[kq*4+3][row]=v.w;
        }
        __syncthreads();
        #pragma unroll
        for (int kk=0;kk<BK;kk++){
            float a_[TM], b_[TN];
            #pragma unroll
            for (int ii=0;ii<TM;ii++) a_[ii] = As[kk][trow*TM+ii];
            #pragma unroll
            for (int jj=0;jj<TN;jj++) b_[jj] = Bs[kk][tcol*TN+jj];
            #pragma unroll
            for (int ii=0;ii<TM;ii++)
                #pragma unroll
                for (int jj=0;jj<TN;jj++)
                    acc[ii][jj] += a_[ii]*b_[jj];
        }
        __syncthreads();
    }

    #pragma unroll
    for (int ii=0;ii<TM;ii++){
        int m = bm + trow*TM + ii;
        #pragma unroll
        for (int jj=0;jj<TN;jj++){
            int n = bn + tcol*TN + jj;
            if (n < N) {
                float bv = bias ? bias[n] : 0.f;
                C[(size_t)m*ldc + n] = acc[ii][jj] + bv;
            }
        }
    }
}

// ---------------- prep: gates, decay, kk norm, pack scan inputs ----------------
// one block per token (512 threads, 4 channels each)
__global__ void __launch_bounds__(512) prep_kernel(
        const float* __restrict__ vfirst,
        const float* __restrict__ w0, const float* __restrict__ a0, const float* __restrict__ v0,
        const float* __restrict__ k_k, const float* __restrict__ k_a, const float* __restrict__ r_k)
{
    int m = blockIdx.x;              // 0..4095
    int b = m / TT, t = m % TT;
    int tid = threadIdx.x;
    int j0 = tid * 4;
    int h  = j0 >> 6;
    int kvidx = (h >> 2)*64 + (j0 & 63);

    float4 rv = *(const float4*)(g_r     + (size_t)m*CC + j0);
    float4 wt = *(const float4*)(g_wterm + (size_t)m*CC + j0);
    float4 at = *(const float4*)(g_aterm + (size_t)m*CC + j0);
    float4 vt = *(const float4*)(g_vterm + (size_t)m*CC + j0);
    float4 kp = *(const float4*)(g_kproj + (size_t)m*KVD + kvidx);
    float4 vp = *(const float4*)(g_vproj + (size_t)m*KVD + kvidx);
    float4 vf = *(const float4*)(vfirst + (size_t)m*CC + j0);
    float4 kkw = *(const float4*)(k_k + j0);
    float4 kaw = *(const float4*)(k_a + j0);
    float4 rkw = *(const float4*)(r_k + j0);
    float4 w0v = *(const float4*)(w0 + j0);
    float4 a0v = *(const float4*)(a0 + j0);
    float4 v0v = *(const float4*)(v0 + j0);

    float rr[4]  = {rv.x, rv.y, rv.z, rv.w};
    float kpv[4] = {kp.x, kp.y, kp.z, kp.w};
    float vpv[4] = {vp.x, vp.y, vp.z, vp.w};
    float wtv[4] = {wt.x, wt.y, wt.z, wt.w};
    float atv[4] = {at.x, at.y, at.z, at.w};
    float vtv[4] = {vt.x, vt.y, vt.z, vt.w};
    float vfv[4] = {vf.x, vf.y, vf.z, vf.w};
    float kkwv[4]= {kkw.x,kkw.y,kkw.z,kkw.w};
    float kawv[4]= {kaw.x,kaw.y,kaw.z,kaw.w};
    float rkv[4] = {rkw.x,rkw.y,rkw.z,rkw.w};
    float w0a[4] = {w0v.x,w0v.y,w0v.z,w0v.w};
    float a0a[4] = {a0v.x,a0v.y,a0v.z,a0v.w};
    float v0a[4] = {v0v.x,v0v.y,v0v.z,v0v.w};

    float aga[4], dec[4], kkpre[4], kmod[4], vb[4];
    float nrm = 0.f;
    #pragma unroll
    for (int c=0;c<4;c++){
        float u = w0a[c] + wtv[c];
        float z = -u;
        float sp = (z > 20.f) ? z : log1pf(expf(z));
        float wraw = -sp - 0.6f;
        dec[c] = expf(-expf(wraw));
        float a = sigmoidf_(a0a[c] + atv[c]);
        aga[c] = a;
        kkpre[c] = kpv[c] * kkwv[c];
        nrm += kkpre[c]*kkpre[c];
        kmod[c] = kpv[c] * (1.f + (a - 1.f) * kawv[c]);
        float vsel = sigmoidf_(v0a[c] + vtv[c]);
        vb[c] = vpv[c] + (vfv[c] - vpv[c]) * vsel;
    }
    float tot = redux16(nrm);
    float inv = 1.f / fmaxf(sqrtf(tot), 1e-12f);

    float kkn[4], aav[4], bbv[4];
    float dsum = 0.f;
    #pragma unroll
    for (int c=0;c<4;c++){
        kkn[c] = kkpre[c]*inv;
        aav[c] = -kkn[c];
        bbv[c] = kkn[c]*aga[c];
        dsum += rr[c]*kmod[c]*rkv[c];
    }
    float dtot = redux16(dsum);
    if ((tid & 15) == 0) g_bcoef[(size_t)m*HH + h] = dtot;

    size_t base = ((size_t)(b*HH + h)*TT + t)*384 + (j0 & 63);
    *(float4*)(g_packed + base +   0) = rv;
    *(float4*)(g_packed + base +  64) = make_float4(dec[0],dec[1],dec[2],dec[3]);
    *(float4*)(g_packed + base + 128) = make_float4(kmod[0],kmod[1],kmod[2],kmod[3]);
    *(float4*)(g_packed + base + 192) = make_float4(vb[0],vb[1],vb[2],vb[3]);
    *(float4*)(g_packed + base + 256) = make_float4(aav[0],aav[1],aav[2],aav[3]);
    *(float4*)(g_packed + base + 320) = make_float4(bbv[0],bbv[1],bbv[2],bbv[3]);
}

// ---------------- recurrent scan: one block per (b,h) ----------------
__global__ void __launch_bounds__(256,1) scan_kernel(const float* __restrict__ state0)
{
    __shared__ float buf[4][384];
    __shared__ float redA[64], redB[64];
    const int bh = blockIdx.x;            // b*32 + h
    const int tid = threadIdx.x;
    const int i = tid >> 2;               // row 0..63
    const int q = tid & 3;                // k-quarter
    const int kb = q * 16;

    float S[16];
    #pragma unroll
    for (int c=0;c<16;c++)
        S[c] = state0[((size_t)bh*64 + i)*64 + kb + c];

    const float* src = g_packed + (size_t)bh*TT*384;

    if (tid < 96) {
        #pragma unroll
        for (int s=0;s<4;s++){
            cp_async16(&buf[s][tid*4], src + (size_t)s*384 + tid*4);
            asm volatile("cp.async.commit_group;\n");
        }
    }

    const int b = bh >> 5, h = bh & 31;
    float* yout = g_y + ((size_t)b*TT*HH + h)*NNd + i;
    float gsum = 0.f, gsq = 0.f;

    for (int t = 0; t < TT; t++) {
        if (tid < 96) asm volatile("cp.async.wait_group 3;\n");
        __syncthreads();
        const float* vbuf = buf[t & 3];

        float rr[16], dd[16], km[16], av[16], bv[16];
        #pragma unroll
        for (int m4=0;m4<4;m4++){
            float4 x0 = *(const float4*)&vbuf[  0 + kb + m4*4];
            float4 x1 = *(const float4*)&vbuf[ 64 + kb + m4*4];
            float4 x2 = *(const float4*)&vbuf[128 + kb + m4*4];
            float4 x4 = *(const float4*)&vbuf[256 + kb + m4*4];
            float4 x5 = *(const float4*)&vbuf[320 + kb + m4*4];
            rr[m4*4+0]=x0.x; rr[m4*4+1]=x0.y; rr[m4*4+2]=x0.z; rr[m4*4+3]=x0.w;
            dd[m4*4+0]=x1.x; dd[m4*4+1]=x1.y; dd[m4*4+2]=x1.z; dd[m4*4+3]=x1.w;
            km[m4*4+0]=x2.x; km[m4*4+1]=x2.y; km[m4*4+2]=x2.z; km[m4*4+3]=x2.w;
            av[m4*4+0]=x4.x; av[m4*4+1]=x4.y; av[m4*4+2]=x4.z; av[m4*4+3]=x4.w;
            bv[m4*4+0]=x5.x; bv[m4*4+1]=x5.y; bv[m4*4+2]=x5.z; bv[m4*4+3]=x5.w;
        }
        float vi = vbuf[192 + i];

        float sa = 0.f;
        #pragma unroll
        for (int c=0;c<16;c++) sa += S[c]*av[c];
        sa += __shfl_xor_sync(0xffffffffu, sa, 1);
        sa += __shfl_xor_sync(0xffffffffu, sa, 2);

        float yp = 0.f;
        #pragma unroll
        for (int c=0;c<16;c++){
            S[c] = S[c]*dd[c] + sa*bv[c] + vi*km[c];
            yp += S[c]*rr[c];
        }
        yp += __shfl_xor_sync(0xffffffffu, yp, 1);
        yp += __shfl_xor_sync(0xffffffffu, yp, 2);

        if (q == 0) {
            yout[(size_t)t*CC] = yp;
            gsum += yp; gsq += yp*yp;
        }
        __syncthreads();
        if (tid < 96) {
            int tt = (t+4 < TT) ? (t+4) : (TT-1);
            cp_async16(&buf[(t+4)&3][tid*4], src + (size_t)tt*384 + tid*4);
            asm volatile("cp.async.commit_group;\n");
        }
    }

    if (q == 0) { redA[i] = gsum; redB[i] = gsq; }
    __syncthreads();
    if (tid < 32) {
        float s1 = redA[tid] + redA[tid+32];
        float s2 = redB[tid] + redB[tid+32];
        #pragma unroll
        for (int off=16; off>=1; off>>=1){
            s1 += __shfl_xor_sync(0xffffffffu, s1, off);
            s2 += __shfl_xor_sync(0xffffffffu, s2, off);
        }
        if (tid == 0) {
            float cnt = (float)(TT*NNd);
            float mean = s1 / cnt;
            float var  = s2 / cnt - mean*mean;
            g_gn[bh*2]   = mean;
            g_gn[bh*2+1] = rsqrtf(var + 0.00064f);
        }
    }
}

// ---------------- groupnorm apply + bonus ----------------
__global__ void __launch_bounds__(512) apply_kernel(
        const float* __restrict__ ln_w, const float* __restrict__ ln_b)
{
    int m = blockIdx.x;
    int b = m / TT, t = m % TT;
    int tid = threadIdx.x;
    int j0 = tid * 4;
    int h = j0 >> 6;

    float mean = g_gn[(b*HH + h)*2];
    float rstd = g_gn[(b*HH + h)*2 + 1];
    float bc   = g_bcoef[(size_t)m*HH + h];

    float4 yv = *(const float4*)(g_y + (size_t)m*CC + j0);
    float4 lw = *(const float4*)(ln_w + j0);
    float4 lb = *(const float4*)(ln_b + j0);
    size_t pbase = ((size_t)(b*HH + h)*TT + t)*384 + (j0 & 63);
    float4 vb = *(const float4*)(g_packed + pbase + 192);

    float4 o;
    o.x = (yv.x - mean)*rstd*lw.x + lb.x + bc*vb.x;
    o.y = (yv.y - mean)*rstd*lw.y + lb.y + bc*vb.y;
    o.z = (yv.z - mean)*rstd*lw.z + lb.z + bc*vb.z;
    o.w = (yv.w - mean)*rstd*lw.w + lb.w + bc*vb.w;
    *(float4*)(g_xx + (size_t)m*CC + j0) = o;
}

// ---------------- launch ----------------
extern "C" void kernel_launch(void* const* d_in, const int* in_sizes, int n_in,
                              void* d_out, int out_size)
{
    const float* x      = (const float*)d_in[0];
    const float* vfirst = (const float*)d_in[1];
    const float* state  = (const float*)d_in[2];
    const float* Rw     = (const float*)d_in[3];
    const float* Rb     = (const float*)d_in[4];
    const float* Kw     = (const float*)d_in[5];
    const float* Kb     = (const float*)d_in[6];
    const float* Vw     = (const float*)d_in[7];
    const float* Vb     = (const float*)d_in[8];
    const float* Ow     = (const float*)d_in[9];
    const float* Ob     = (const float*)d_in[10];
    const float* w0     = (const float*)d_in[11];
    const float* w1     = (const float*)d_in[12];
    const float* w2     = (const float*)d_in[13];
    const float* a0     = (const float*)d_in[14];
    const float* a1     = (const float*)d_in[15];
    const float* a2     = (const float*)d_in[16];
    const float* v0     = (const float*)d_in[17];
    const float* v1     = (const float*)d_in[18];
    const float* v2     = (const float*)d_in[19];
    const float* k_k    = (const float*)d_in[20];
    const float* k_a    = (const float*)d_in[21];
    const float* r_k    = (const float*)d_in[22];
    const float* ln_w   = (const float*)d_in[23];
    const float* ln_b   = (const float*)d_in[24];
    float* out = (float*)d_out;

    float *hid, *r_, *kp, *vp, *wt, *at, *vt, *xx, *WhT, *w2T, *a2T, *v2T;
    cudaGetSymbolAddress((void**)&hid, g_hidden);
    cudaGetSymbolAddress((void**)&r_,  g_r);
    cudaGetSymbolAddress((void**)&kp,  g_kproj);
    cudaGetSymbolAddress((void**)&vp,  g_vproj);
    cudaGetSymbolAddress((void**)&wt,  g_wterm);
    cudaGetSymbolAddress((void**)&at,  g_aterm);
    cudaGetSymbolAddress((void**)&vt,  g_vterm);
    cudaGetSymbolAddress((void**)&xx,  g_xx);
    cudaGetSymbolAddress((void**)&WhT, g_WhT);
    cudaGetSymbolAddress((void**)&w2T, g_w2T);
    cudaGetSymbolAddress((void**)&a2T, g_a2T);
    cudaGetSymbolAddress((void**)&v2T, g_v2T);

    pack_weights<<<128, 256>>>(w1, a1, v1, w2, a2, v2);

    // big projections: r, kproj, vproj (NT GEMM, A=x)
    {
        dim3 g(CC/128, MM/128);
        sgemm_nt<128,128,8,8,8><<<g, 256>>>(x, CC, Rw, CC, Rb, r_, CC, MM, CC, CC);
    }
    {
        dim3 g(KVD/128, MM/128);
        sgemm_nt<128,128,8,8,8><<<g, 256>>>(x, CC, Kw, CC, Kb, kp, KVD, MM, KVD, CC);
        sgemm_nt<128,128,8,8,8><<<g, 256>>>(x, CC, Vw, CC, Vb, vp, KVD, MM, KVD, CC);
    }
    // hidden = x @ [w1|a1|v1]  (N=160)
    {
        dim3 g((160+127)/128, MM/128);
        sgemm_nt<128,128,8,8,8><<<g, 256>>>(x, CC, WhT, CC, nullptr, hid, 160, MM, 160, CC);
    }
    tanh_hidden<<<(MM*64+255)/256, 256>>>();
    // stage-2 small-K GEMMs
    {
        dim3 g(CC/128, MM/128);
        sgemm_nt<128,128,8,8,8><<<g, 256>>>(hid,      160, w2T, 64, nullptr, wt, CC, MM, CC, 64);
        sgemm_nt<128,128,8,8,8><<<g, 256>>>(hid+64,   160, a2T, 64, nullptr, at, CC, MM, CC, 64);
        sgemm_nt<128,128,8,8,8><<<g, 256>>>(hid+128,  160, v2T, 32, nullptr, vt, CC, MM, CC, 32);
    }

    prep_kernel<<<MM, 512>>>(vfirst, w0, a0, v0, k_k, k_a, r_k);
    scan_kernel<<<BB*HH, 256>>>(state);
    apply_kernel<<<MM, 512>>>(ln_w, ln_b);

    // out = xx @ O^T + O_bias
    {
        dim3 g(CC/128, MM/128);
        sgemm_nt<128,128,8,8,8><<<g, 256>>>(xx, CC, Ow, CC, Ob, out, CC, MM, CC, CC);
    }
}

// round 8
// speedup vs baseline: 2.3160x; 2.3160x over previous
#include <cuda_runtime.h>
#include <cuda_bf16.h>
#include <math.h>
#include <stdint.h>

#define BB 4
#define TT 1024
#define CC 2048
#define HH 32
#define NNd 64
#define KVD 512
#define MM (BB*TT)      // 4096 tokens
#define N1 3328         // combined GEMM1 N: 2048(R)+512(K)+512(V)+160(lora)+96 pad
#define HIDP 192        // hidden padded cols

// ---------------- scratch (static device arrays; no allocation) ----------------
__device__ __align__(128) __nv_bfloat16 g_xhi[(size_t)MM*CC];
__device__ __align__(128) __nv_bfloat16 g_xlo[(size_t)MM*CC];
__device__ __align__(128) __nv_bfloat16 g_b1hi[(size_t)N1*CC];
__device__ __align__(128) __nv_bfloat16 g_b1lo[(size_t)N1*CC];
__device__ __align__(128) float g_bias1[N1];
__device__ __align__(128) float g_proj[(size_t)MM*N1];
__device__ __align__(128) __nv_bfloat16 g_hidhi[(size_t)MM*HIDP];
__device__ __align__(128) __nv_bfloat16 g_hidlo[(size_t)MM*HIDP];
__device__ __align__(128) __nv_bfloat16 g_w2hi[CC*64];
__device__ __align__(128) __nv_bfloat16 g_w2lo[CC*64];
__device__ __align__(128) __nv_bfloat16 g_a2hi[CC*64];
__device__ __align__(128) __nv_bfloat16 g_a2lo[CC*64];
__device__ __align__(128) __nv_bfloat16 g_v2hi[CC*64];
__device__ __align__(128) __nv_bfloat16 g_v2lo[CC*64];
__device__ __align__(128) float g_wterm[(size_t)MM*CC];
__device__ __align__(128) float g_aterm[(size_t)MM*CC];
__device__ __align__(128) float g_vterm[(size_t)MM*CC];
__device__ __align__(128) float g_packed[(size_t)BB*HH*TT*384];
__device__ __align__(128) float g_y[(size_t)MM*CC];
__device__ __align__(128) __nv_bfloat16 g_xxhi[(size_t)MM*CC];
__device__ __align__(128) __nv_bfloat16 g_xxlo[(size_t)MM*CC];
__device__ __align__(128) __nv_bfloat16 g_ohi[(size_t)CC*CC];
__device__ __align__(128) __nv_bfloat16 g_olo[(size_t)CC*CC];
__device__ __align__(128) float g_bcoef[(size_t)MM*HH];
__device__ __align__(128) float g_gn[BB*HH*2];

// ---------------- helpers ----------------
__device__ __forceinline__ float sigmoidf_(float x){ return 1.0f/(1.0f + expf(-x)); }

__device__ __forceinline__ float redux16(float v){
    v += __shfl_xor_sync(0xffffffffu, v, 1);
    v += __shfl_xor_sync(0xffffffffu, v, 2);
    v += __shfl_xor_sync(0xffffffffu, v, 4);
    v += __shfl_xor_sync(0xffffffffu, v, 8);
    return v;
}

__device__ __forceinline__ void cp_async16(void* smem, const void* gmem){
    unsigned s = (unsigned)__cvta_generic_to_shared(smem);
    asm volatile("cp.async.cg.shared.global [%0], [%1], 16;\n" :: "r"(s), "l"(gmem));
}

__device__ __forceinline__ void split2(float v, __nv_bfloat16* hi, __nv_bfloat16* lo){
    __nv_bfloat16 h = __float2bfloat16(v);
    *hi = h;
    *lo = __float2bfloat16(v - __bfloat162float(h));
}

// ---------------- mma.sync helpers (legacy tensor path; works on plain sm_103 target) ----
__device__ __forceinline__ void ldsm4(uint32_t* r, uint32_t addr){
    asm volatile("ldmatrix.sync.aligned.m8n8.x4.shared.b16 {%0,%1,%2,%3}, [%4];"
                 : "=r"(r[0]), "=r"(r[1]), "=r"(r[2]), "=r"(r[3]) : "r"(addr));
}

__device__ __forceinline__ void mma16816(float* c, const uint32_t* a, const uint32_t* b){
    asm volatile(
        "mma.sync.aligned.m16n8k16.row.col.f32.bf16.bf16.f32 "
        "{%0,%1,%2,%3}, {%4,%5,%6,%7}, {%8,%9}, {%0,%1,%2,%3};"
        : "+f"(c[0]), "+f"(c[1]), "+f"(c[2]), "+f"(c[3])
        : "r"(a[0]), "r"(a[1]), "r"(a[2]), "r"(a[3]), "r"(b[0]), "r"(b[1]));
}

// ---------------- packing / split kernels ----------------
__global__ void pack_b1(const float* __restrict__ R,  const float* __restrict__ Rb,
                        const float* __restrict__ Kw, const float* __restrict__ Kb,
                        const float* __restrict__ Vw, const float* __restrict__ Vb,
                        const float* __restrict__ w1, const float* __restrict__ a1,
                        const float* __restrict__ v1)
{
    size_t idx = (size_t)blockIdx.x*blockDim.x + threadIdx.x;
    if (idx < N1) {
        float bv = 0.f;
        if (idx < 2048) bv = Rb[idx];
        else if (idx < 2560) bv = Kb[idx-2048];
        else if (idx < 3072) bv = Vb[idx-2560];
        g_bias1[idx] = bv;
    }
    if (idx >= (size_t)N1*CC) return;
    int n = (int)(idx / CC), k = (int)(idx % CC);
    float v = 0.f;
    if      (n < 2048) v = R [(size_t)n*CC + k];
    else if (n < 2560) v = Kw[(size_t)(n-2048)*CC + k];
    else if (n < 3072) v = Vw[(size_t)(n-2560)*CC + k];
    else if (n < 3136) v = w1[(size_t)k*64 + (n-3072)];
    else if (n < 3200) v = a1[(size_t)k*64 + (n-3136)];
    else if (n < 3232) v = v1[(size_t)k*32 + (n-3200)];
    split2(v, &g_b1hi[idx], &g_b1lo[idx]);
}

__global__ void pack_b2(const float* __restrict__ w2, const float* __restrict__ a2,
                        const float* __restrict__ v2)
{
    int idx = blockIdx.x*blockDim.x + threadIdx.x;
    if (idx >= CC*64) return;
    int n = idx / 64, k = idx % 64;
    split2(w2[(size_t)k*CC + n], &g_w2hi[idx], &g_w2lo[idx]);
    split2(a2[(size_t)k*CC + n], &g_a2hi[idx], &g_a2lo[idx]);
    float vv = (k < 32) ? v2[(size_t)k*CC + n] : 0.f;
    split2(vv, &g_v2hi[idx], &g_v2lo[idx]);
}

__global__ void split_fp32(const float* __restrict__ src,
                           __nv_bfloat16* __restrict__ hi, __nv_bfloat16* __restrict__ lo,
                           size_t n)
{
    size_t i = (size_t)blockIdx.x*blockDim.x + threadIdx.x;
    if (i < n) split2(src[i], &hi[i], &lo[i]);
}

__global__ void hid_split()
{
    size_t idx = (size_t)blockIdx.x*blockDim.x + threadIdx.x;
    if (idx >= (size_t)MM*HIDP) return;
    int m = (int)(idx / HIDP), j = (int)(idx % HIDP);
    const float* row = g_proj + (size_t)m*N1 + 3072;
    float v = 0.f;
    if (j < 64)       v = tanhf(row[j]);
    else if (j < 160) v = row[j];
    split2(v, &g_hidhi[idx], &g_hidlo[idx]);
}

// ---------------- split-bf16 HMMA NT GEMM: C = (Ahi+Alo)(Bhi+Blo)^T + bias --------
// BM=BN=128, BK=32, 256 threads (8 warps, warp tile 64x32), cp.async double buffer.
#define SPAD 40                     // smem row stride in bf16 elems (32 + 8 pad)
#define TILEB (128*SPAD*2)          // 10240 B per operand tile
#define STAGEB (4*TILEB)            // 40960 B per stage

__global__ void __launch_bounds__(256,2) hmma_nt(
    const __nv_bfloat16* __restrict__ Ahi, const __nv_bfloat16* __restrict__ Alo, int lda,
    const __nv_bfloat16* __restrict__ Bhi, const __nv_bfloat16* __restrict__ Blo, int ldb,
    const float* __restrict__ bias, float* __restrict__ Cc, int ldc, int KT)
{
    extern __shared__ __align__(128) char smem[];
    const int tid  = threadIdx.x;
    const int warp = tid >> 5;
    const int lane = tid & 31;
    const int bm   = blockIdx.y * 128;
    const int bn   = blockIdx.x * 128;
    const int wm   = (warp & 1) * 64;   // warp row base within block
    const int wn   = (warp >> 1) * 32;  // warp col base within block

    float acc[4][4][4];
    #pragma unroll
    for (int a=0;a<4;a++)
        #pragma unroll
        for (int b=0;b<4;b++)
            #pragma unroll
            for (int c=0;c<4;c++) acc[a][b][c]=0.f;

    auto load_stage = [&](int stage, int kt){
        const int k0 = kt * 32;
        char* sb = smem + stage * STAGEB;
        const __nv_bfloat16* bases[4];
        int lds[4];
        bases[0] = Ahi + (size_t)bm*lda + k0; lds[0] = lda;
        bases[1] = Alo + (size_t)bm*lda + k0; lds[1] = lda;
        bases[2] = Bhi + (size_t)bn*ldb + k0; lds[2] = ldb;
        bases[3] = Blo + (size_t)bn*ldb + k0; lds[3] = ldb;
        #pragma unroll
        for (int t = 0; t < 4; t++){
            #pragma unroll
            for (int it = 0; it < 2; it++){
                int idx = it*256 + tid;         // 0..511
                int r = idx >> 2, c = idx & 3;  // row, 16B chunk
                cp_async16(sb + t*TILEB + (r*SPAD + c*8)*2,
                           bases[t] + (size_t)r*lds[t] + c*8);
            }
        }
        asm volatile("cp.async.commit_group;" ::: "memory");
    };

    load_stage(0, 0);

    const uint32_t sbase = (uint32_t)__cvta_generic_to_shared(smem);

    for (int kt = 0; kt < KT; kt++){
        const int buf = kt & 1;
        if (kt + 1 < KT){
            load_stage(buf ^ 1, kt + 1);
            asm volatile("cp.async.wait_group 1;" ::: "memory");
        } else {
            asm volatile("cp.async.wait_group 0;" ::: "memory");
        }
        __syncthreads();

        const uint32_t sA_hi = sbase + buf*STAGEB;
        const uint32_t sA_lo = sA_hi + TILEB;
        const uint32_t sB_hi = sA_hi + 2*TILEB;
        const uint32_t sB_lo = sA_hi + 3*TILEB;

        #pragma unroll
        for (int ks = 0; ks < 2; ks++){
            uint32_t aF[4][4], bH[2][4], bL[2][4];
            // B fragments: one x4 covers 2 n-frags (n16 x k16)
            #pragma unroll
            for (int half = 0; half < 2; half++){
                int nrow = wn + half*16 + (lane & 7) + ((lane >> 4) << 3);
                int ncol = ks*16 + ((lane >> 3) & 1)*8;
                uint32_t off = (uint32_t)(nrow*SPAD + ncol)*2;
                ldsm4(bH[half], sB_hi + off);
                ldsm4(bL[half], sB_lo + off);
            }
            // A hi fragments
            #pragma unroll
            for (int mf = 0; mf < 4; mf++){
                int arow = wm + mf*16 + (lane & 15);
                int acol = ks*16 + (lane >> 4)*8;
                ldsm4(aF[mf], sA_hi + (uint32_t)(arow*SPAD + acol)*2);
            }
            #pragma unroll
            for (int mf = 0; mf < 4; mf++)
                #pragma unroll
                for (int nf = 0; nf < 4; nf++){
                    mma16816(acc[mf][nf], aF[mf], &bH[nf>>1][(nf&1)*2]);
                    mma16816(acc[mf][nf], aF[mf], &bL[nf>>1][(nf&1)*2]);
                }
            // A lo fragments (reuse regs)
            #pragma unroll
            for (int mf = 0; mf < 4; mf++){
                int arow = wm + mf*16 + (lane & 15);
                int acol = ks*16 + (lane >> 4)*8;
                ldsm4(aF[mf], sA_lo + (uint32_t)(arow*SPAD + acol)*2);
            }
            #pragma unroll
            for (int mf = 0; mf < 4; mf++)
                #pragma unroll
                for (int nf = 0; nf < 4; nf++)
                    mma16816(acc[mf][nf], aF[mf], &bH[nf>>1][(nf&1)*2]);
        }
        __syncthreads();
    }

    // epilogue
    #pragma unroll
    for (int mf = 0; mf < 4; mf++){
        #pragma unroll
        for (int nf = 0; nf < 4; nf++){
            int row0 = bm + wm + mf*16 + (lane >> 2);
            int col0 = bn + wn + nf*8  + (lane & 3)*2;
            float b0 = 0.f, b1 = 0.f;
            if (bias){ b0 = bias[col0]; b1 = bias[col0+1]; }
            float2 v0 = make_float2(acc[mf][nf][0] + b0, acc[mf][nf][1] + b1);
            float2 v1 = make_float2(acc[mf][nf][2] + b0, acc[mf][nf][3] + b1);
            *(float2*)(Cc + (size_t)row0*ldc + col0)       = v0;
            *(float2*)(Cc + (size_t)(row0+8)*ldc + col0)   = v1;
        }
    }
}

// ---------------- prep: gates, decay, kk norm, pack scan inputs ----------------
__global__ void __launch_bounds__(512) prep_kernel(
        const float* __restrict__ vfirst,
        const float* __restrict__ w0, const float* __restrict__ a0, const float* __restrict__ v0,
        const float* __restrict__ k_k, const float* __restrict__ k_a, const float* __restrict__ r_k)
{
    int m = blockIdx.x;
    int b = m / TT, t = m % TT;
    int tid = threadIdx.x;
    int j0 = tid * 4;
    int h  = j0 >> 6;
    int kvidx = (h >> 2)*64 + (j0 & 63);

    const float* prow = g_proj + (size_t)m*N1;
    float4 rv = *(const float4*)(prow + j0);
    float4 kp = *(const float4*)(prow + 2048 + kvidx);
    float4 vp = *(const float4*)(prow + 2560 + kvidx);
    float4 wt = *(const float4*)(g_wterm + (size_t)m*CC + j0);
    float4 at = *(const float4*)(g_aterm + (size_t)m*CC + j0);
    float4 vt = *(const float4*)(g_vterm + (size_t)m*CC + j0);
    float4 vf = *(const float4*)(vfirst + (size_t)m*CC + j0);
    float4 kkw = *(const float4*)(k_k + j0);
    float4 kaw = *(const float4*)(k_a + j0);
    float4 rkw = *(const float4*)(r_k + j0);
    float4 w0v = *(const float4*)(w0 + j0);
    float4 a0v = *(const float4*)(a0 + j0);
    float4 v0v = *(const float4*)(v0 + j0);

    float rr[4]  = {rv.x, rv.y, rv.z, rv.w};
    float kpv[4] = {kp.x, kp.y, kp.z, kp.w};
    float vpv[4] = {vp.x, vp.y, vp.z, vp.w};
    float wtv[4] = {wt.x, wt.y, wt.z, wt.w};
    float atv[4] = {at.x, at.y, at.z, at.w};
    float vtv[4] = {vt.x, vt.y, vt.z, vt.w};
    float vfv[4] = {vf.x, vf.y, vf.z, vf.w};
    float kkwv[4]= {kkw.x,kkw.y,kkw.z,kkw.w};
    float kawv[4]= {kaw.x,kaw.y,kaw.z,kaw.w};
    float rkv[4] = {rkw.x,rkw.y,rkw.z,rkw.w};
    float w0a[4] = {w0v.x,w0v.y,w0v.z,w0v.w};
    float a0a[4] = {a0v.x,a0v.y,a0v.z,a0v.w};
    float v0a[4] = {v0v.x,v0v.y,v0v.z,v0v.w};

    float aga[4], dec[4], kkpre[4], kmod[4], vb[4];
    float nrm = 0.f;
    #pragma unroll
    for (int c=0;c<4;c++){
        float u = w0a[c] + wtv[c];
        float z = -u;
        float sp = (z > 20.f) ? z : log1pf(expf(z));
        float wraw = -sp - 0.6f;
        dec[c] = expf(-expf(wraw));
        float a = sigmoidf_(a0a[c] + atv[c]);
        aga[c] = a;
        kkpre[c] = kpv[c] * kkwv[c];
        nrm += kkpre[c]*kkpre[c];
        kmod[c] = kpv[c] * (1.f + (a - 1.f) * kawv[c]);
        float vsel = sigmoidf_(v0a[c] + vtv[c]);
        vb[c] = vpv[c] + (vfv[c] - vpv[c]) * vsel;
    }
    float tot = redux16(nrm);
    float inv = 1.f / fmaxf(sqrtf(tot), 1e-12f);

    float aav[4], bbv[4];
    float dsum = 0.f;
    #pragma unroll
    for (int c=0;c<4;c++){
        float kkn = kkpre[c]*inv;
        aav[c] = -kkn;
        bbv[c] = kkn*aga[c];
        dsum += rr[c]*kmod[c]*rkv[c];
    }
    float dtot = redux16(dsum);
    if ((tid & 15) == 0) g_bcoef[(size_t)m*HH + h] = dtot;

    size_t base = ((size_t)(b*HH + h)*TT + t)*384 + (j0 & 63);
    *(float4*)(g_packed + base +   0) = rv;
    *(float4*)(g_packed + base +  64) = make_float4(dec[0],dec[1],dec[2],dec[3]);
    *(float4*)(g_packed + base + 128) = make_float4(kmod[0],kmod[1],kmod[2],kmod[3]);
    *(float4*)(g_packed + base + 192) = make_float4(vb[0],vb[1],vb[2],vb[3]);
    *(float4*)(g_packed + base + 256) = make_float4(aav[0],aav[1],aav[2],aav[3]);
    *(float4*)(g_packed + base + 320) = make_float4(bbv[0],bbv[1],bbv[2],bbv[3]);
}

// ---------------- recurrent scan: one block per (b,h) ----------------
__global__ void __launch_bounds__(256,1) scan_kernel(const float* __restrict__ state0)
{
    __shared__ float buf[4][384];
    __shared__ float redA[64], redB[64];
    const int bh = blockIdx.x;
    const int tid = threadIdx.x;
    const int i = tid >> 2;
    const int q = tid & 3;
    const int kb = q * 16;

    float S[16];
    #pragma unroll
    for (int c=0;c<16;c++)
        S[c] = state0[((size_t)bh*64 + i)*64 + kb + c];

    const float* src = g_packed + (size_t)bh*TT*384;

    if (tid < 96) {
        #pragma unroll
        for (int s=0;s<4;s++){
            cp_async16(&buf[s][tid*4], src + (size_t)s*384 + tid*4);
            asm volatile("cp.async.commit_group;\n");
        }
    }

    const int b = bh >> 5, h = bh & 31;
    float* yout = g_y + ((size_t)b*TT*HH + h)*NNd + i;
    float gsum = 0.f, gsq = 0.f;

    for (int t = 0; t < TT; t++) {
        if (tid < 96) asm volatile("cp.async.wait_group 3;\n");
        __syncthreads();
        const float* vbuf = buf[t & 3];

        float rr[16], dd[16], km[16], av[16], bv[16];
        #pragma unroll
        for (int m4=0;m4<4;m4++){
            float4 x0 = *(const float4*)&vbuf[  0 + kb + m4*4];
            float4 x1 = *(const float4*)&vbuf[ 64 + kb + m4*4];
            float4 x2 = *(const float4*)&vbuf[128 + kb + m4*4];
            float4 x4 = *(const float4*)&vbuf[256 + kb + m4*4];
            float4 x5 = *(const float4*)&vbuf[320 + kb + m4*4];
            rr[m4*4+0]=x0.x; rr[m4*4+1]=x0.y; rr[m4*4+2]=x0.z; rr[m4*4+3]=x0.w;
            dd[m4*4+0]=x1.x; dd[m4*4+1]=x1.y; dd[m4*4+2]=x1.z; dd[m4*4+3]=x1.w;
            km[m4*4+0]=x2.x; km[m4*4+1]=x2.y; km[m4*4+2]=x2.z; km[m4*4+3]=x2.w;
            av[m4*4+0]=x4.x; av[m4*4+1]=x4.y; av[m4*4+2]=x4.z; av[m4*4+3]=x4.w;
            bv[m4*4+0]=x5.x; bv[m4*4+1]=x5.y; bv[m4*4+2]=x5.z; bv[m4*4+3]=x5.w;
        }
        float vi = vbuf[192 + i];

        float sa = 0.f;
        #pragma unroll
        for (int c=0;c<16;c++) sa += S[c]*av[c];
        sa += __shfl_xor_sync(0xffffffffu, sa, 1);
        sa += __shfl_xor_sync(0xffffffffu, sa, 2);

        float yp = 0.f;
        #pragma unroll
        for (int c=0;c<16;c++){
            S[c] = S[c]*dd[c] + sa*bv[c] + vi*km[c];
            yp += S[c]*rr[c];
        }
        yp += __shfl_xor_sync(0xffffffffu, yp, 1);
        yp += __shfl_xor_sync(0xffffffffu, yp, 2);

        if (q == 0) {
            yout[(size_t)t*CC] = yp;
            gsum += yp; gsq += yp*yp;
        }
        __syncthreads();
        if (tid < 96) {
            int tt = (t+4 < TT) ? (t+4) : (TT-1);
            cp_async16(&buf[(t+4)&3][tid*4], src + (size_t)tt*384 + tid*4);
            asm volatile("cp.async.commit_group;\n");
        }
    }

    if (q == 0) { redA[i] = gsum; redB[i] = gsq; }
    __syncthreads();
    if (tid < 32) {
        float s1 = redA[tid] + redA[tid+32];
        float s2 = redB[tid] + redB[tid+32];
        #pragma unroll
        for (int off=16; off>=1; off>>=1){
            s1 += __shfl_xor_sync(0xffffffffu, s1, off);
            s2 += __shfl_xor_sync(0xffffffffu, s2, off);
        }
        if (tid == 0) {
            float cnt = (float)(TT*NNd);
            float mean = s1 / cnt;
            float var  = s2 / cnt - mean*mean;
            g_gn[bh*2]   = mean;
            g_gn[bh*2+1] = rsqrtf(var + 0.00064f);
        }
    }
}

// ---------------- groupnorm apply + bonus, fused bf16 split ----------------
__global__ void __launch_bounds__(512) apply_kernel(
        const float* __restrict__ ln_w, const float* __restrict__ ln_b)
{
    int m = blockIdx.x;
    int b = m / TT, t = m % TT;
    int tid = threadIdx.x;
    int j0 = tid * 4;
    int h = j0 >> 6;

    float mean = g_gn[(b*HH + h)*2];
    float rstd = g_gn[(b*HH + h)*2 + 1];
    float bc   = g_bcoef[(size_t)m*HH + h];

    float4 yv = *(const float4*)(g_y + (size_t)m*CC + j0);
    float4 lw = *(const float4*)(ln_w + j0);
    float4 lb = *(const float4*)(ln_b + j0);
    size_t pbase = ((size_t)(b*HH + h)*TT + t)*384 + (j0 & 63);
    float4 vb = *(const float4*)(g_packed + pbase + 192);

    float o[4];
    o[0] = (yv.x - mean)*rstd*lw.x + lb.x + bc*vb.x;
    o[1] = (yv.y - mean)*rstd*lw.y + lb.y + bc*vb.y;
    o[2] = (yv.z - mean)*rstd*lw.z + lb.z + bc*vb.z;
    o[3] = (yv.w - mean)*rstd*lw.w + lb.w + bc*vb.w;

    __nv_bfloat16 hi[4], lo[4];
    #pragma unroll
    for (int c=0;c<4;c++) split2(o[c], &hi[c], &lo[c]);
    *(uint2*)(g_xxhi + (size_t)m*CC + j0) = *(uint2*)hi;
    *(uint2*)(g_xxlo + (size_t)m*CC + j0) = *(uint2*)lo;
}

// ---------------- launch ----------------
extern "C" void kernel_launch(void* const* d_in, const int* in_sizes, int n_in,
                              void* d_out, int out_size)
{
    const float* x      = (const float*)d_in[0];
    const float* vfirst = (const float*)d_in[1];
    const float* state  = (const float*)d_in[2];
    const float* Rw     = (const float*)d_in[3];
    const float* Rb     = (const float*)d_in[4];
    const float* Kw     = (const float*)d_in[5];
    const float* Kb     = (const float*)d_in[6];
    const float* Vw     = (const float*)d_in[7];
    const float* Vb     = (const float*)d_in[8];
    const float* Ow     = (const float*)d_in[9];
    const float* Ob     = (const float*)d_in[10];
    const float* w0     = (const float*)d_in[11];
    const float* w1     = (const float*)d_in[12];
    const float* w2     = (const float*)d_in[13];
    const float* a0     = (const float*)d_in[14];
    const float* a1     = (const float*)d_in[15];
    const float* a2     = (const float*)d_in[16];
    const float* v0     = (const float*)d_in[17];
    const float* v1     = (const float*)d_in[18];
    const float* v2     = (const float*)d_in[19];
    const float* k_k    = (const float*)d_in[20];
    const float* k_a    = (const float*)d_in[21];
    const float* r_k    = (const float*)d_in[22];
    const float* ln_w   = (const float*)d_in[23];
    const float* ln_b   = (const float*)d_in[24];
    float* out = (float*)d_out;

    cudaFuncSetAttribute(hmma_nt, cudaFuncAttributeMaxDynamicSharedMemorySize, 2*STAGEB);

    float *proj, *wterm, *aterm, *vterm, *bias1;
    __nv_bfloat16 *xhi, *xlo, *b1hi, *b1lo, *hhi, *hlo;
    __nv_bfloat16 *w2hi, *w2lo, *a2hi, *a2lo, *v2hi, *v2lo;
    __nv_bfloat16 *xxhi, *xxlo, *ohi, *olo;
    cudaGetSymbolAddress((void**)&proj,  g_proj);
    cudaGetSymbolAddress((void**)&wterm, g_wterm);
    cudaGetSymbolAddress((void**)&aterm, g_aterm);
    cudaGetSymbolAddress((void**)&vterm, g_vterm);
    cudaGetSymbolAddress((void**)&bias1, g_bias1);
    cudaGetSymbolAddress((void**)&xhi,   g_xhi);
    cudaGetSymbolAddress((void**)&xlo,   g_xlo);
    cudaGetSymbolAddress((void**)&b1hi,  g_b1hi);
    cudaGetSymbolAddress((void**)&b1lo,  g_b1lo);
    cudaGetSymbolAddress((void**)&hhi,   g_hidhi);
    cudaGetSymbolAddress((void**)&hlo,   g_hidlo);
    cudaGetSymbolAddress((void**)&w2hi,  g_w2hi);
    cudaGetSymbolAddress((void**)&w2lo,  g_w2lo);
    cudaGetSymbolAddress((void**)&a2hi,  g_a2hi);
    cudaGetSymbolAddress((void**)&a2lo,  g_a2lo);
    cudaGetSymbolAddress((void**)&v2hi,  g_v2hi);
    cudaGetSymbolAddress((void**)&v2lo,  g_v2lo);
    cudaGetSymbolAddress((void**)&xxhi,  g_xxhi);
    cudaGetSymbolAddress((void**)&xxlo,  g_xxlo);
    cudaGetSymbolAddress((void**)&ohi,   g_ohi);
    cudaGetSymbolAddress((void**)&olo,   g_olo);

    // weight/activation packing + splits
    pack_b1<<<(int)(((size_t)N1*CC + 255)/256), 256>>>(Rw, Rb, Kw, Kb, Vw, Vb, w1, a1, v1);
    pack_b2<<<(CC*64 + 255)/256, 256>>>(w2, a2, v2);
    split_fp32<<<(int)(((size_t)MM*CC + 255)/256), 256>>>(x, xhi, xlo, (size_t)MM*CC);
    split_fp32<<<(int)(((size_t)CC*CC + 255)/256), 256>>>(Ow, ohi, olo, (size_t)CC*CC);

    // GEMM1: proj = x @ [R|K|V|w1|a1|v1]^T + bias1   (M=4096, N=3328, K=2048)
    {
        dim3 g(N1/128, MM/128);
        hmma_nt<<<g, 256, 2*STAGEB>>>(xhi, xlo, CC, b1hi, b1lo, CC, bias1, proj, N1, CC/32);
    }
    hid_split<<<(int)(((size_t)MM*HIDP + 255)/256), 256>>>();

    // stage-2 small-K GEMMs (K=64 -> KT=2)
    {
        dim3 g(CC/128, MM/128);
        hmma_nt<<<g, 256, 2*STAGEB>>>(hhi,       hlo,       HIDP, w2hi, w2lo, 64, nullptr, wterm, CC, 2);
        hmma_nt<<<g, 256, 2*STAGEB>>>(hhi + 64,  hlo + 64,  HIDP, a2hi, a2lo, 64, nullptr, aterm, CC, 2);
        hmma_nt<<<g, 256, 2*STAGEB>>>(hhi + 128, hlo + 128, HIDP, v2hi, v2lo, 64, nullptr, vterm, CC, 2);
    }

    prep_kernel<<<MM, 512>>>(vfirst, w0, a0, v0, k_k, k_a, r_k);
    scan_kernel<<<BB*HH, 256>>>(state);
    apply_kernel<<<MM, 512>>>(ln_w, ln_b);

    // out = xx @ O^T + O_bias   (M=4096, N=2048, K=2048)
    {
        dim3 g(CC/128, MM/128);
        hmma_nt<<<g, 256, 2*STAGEB>>>(xxhi, xxlo, CC, ohi, olo, CC, Ob, out, CC, CC/32);
    }
}

// round 9
// speedup vs baseline: 2.7382x; 1.1823x over previous
#include <cuda_runtime.h>
#include <cuda_fp16.h>
#include <math.h>
#include <stdint.h>

#define BB 4
#define TT 1024
#define CC 2048
#define HH 32
#define NNd 64
#define KVD 512
#define MM (BB*TT)      // 4096 tokens
#define N1 3328         // combined GEMM1 N: 2048(R)+512(K)+512(V)+160(lora)+96 pad
#define HIDP 192        // hidden padded cols

// ---------------- scratch (static device arrays; no allocation) ----------------
__device__ __align__(128) __half g_xh[(size_t)MM*CC];
__device__ __align__(128) __half g_b1hi[(size_t)N1*CC];
__device__ __align__(128) __half g_b1lo[(size_t)N1*CC];
__device__ __align__(128) float g_bias1[N1];
__device__ __align__(128) float g_proj[(size_t)MM*N1];
__device__ __align__(128) __half g_hidh[(size_t)MM*HIDP];
__device__ __align__(128) __half g_w2hi[CC*64];
__device__ __align__(128) __half g_w2lo[CC*64];
__device__ __align__(128) __half g_a2hi[CC*64];
__device__ __align__(128) __half g_a2lo[CC*64];
__device__ __align__(128) __half g_v2hi[CC*64];
__device__ __align__(128) __half g_v2lo[CC*64];
__device__ __align__(128) float g_wterm[(size_t)MM*CC];
__device__ __align__(128) float g_aterm[(size_t)MM*CC];
__device__ __align__(128) float g_vterm[(size_t)MM*CC];
__device__ __align__(128) float g_packed[(size_t)BB*HH*TT*384];
__device__ __align__(128) float g_y[(size_t)MM*CC];
__device__ __align__(128) __half g_xxh[(size_t)MM*CC];
__device__ __align__(128) __half g_ohi[(size_t)CC*CC];
__device__ __align__(128) __half g_olo[(size_t)CC*CC];
__device__ __align__(128) float g_bcoef[(size_t)MM*HH];
__device__ __align__(128) float g_gn[BB*HH*2];

// ---------------- helpers ----------------
__device__ __forceinline__ float sigmoidf_(float x){ return 1.0f/(1.0f + expf(-x)); }

__device__ __forceinline__ float redux16(float v){
    v += __shfl_xor_sync(0xffffffffu, v, 1);
    v += __shfl_xor_sync(0xffffffffu, v, 2);
    v += __shfl_xor_sync(0xffffffffu, v, 4);
    v += __shfl_xor_sync(0xffffffffu, v, 8);
    return v;
}

__device__ __forceinline__ void cp_async16(void* smem, const void* gmem){
    unsigned s = (unsigned)__cvta_generic_to_shared(smem);
    asm volatile("cp.async.cg.shared.global [%0], [%1], 16;\n" :: "r"(s), "l"(gmem));
}

__device__ __forceinline__ void split2h(float v, __half* hi, __half* lo){
    __half h = __float2half_rn(v);
    *hi = h;
    *lo = __float2half_rn(v - __half2float(h));
}

// ---------------- mma.sync helpers (legacy tensor path; plain sm_103 target) ----
__device__ __forceinline__ void ldsm4(uint32_t* r, uint32_t addr){
    asm volatile("ldmatrix.sync.aligned.m8n8.x4.shared.b16 {%0,%1,%2,%3}, [%4];"
                 : "=r"(r[0]), "=r"(r[1]), "=r"(r[2]), "=r"(r[3]) : "r"(addr));
}

__device__ __forceinline__ void mma16816(float* c, const uint32_t* a, const uint32_t* b){
    asm volatile(
        "mma.sync.aligned.m16n8k16.row.col.f32.f16.f16.f32 "
        "{%0,%1,%2,%3}, {%4,%5,%6,%7}, {%8,%9}, {%0,%1,%2,%3};"
        : "+f"(c[0]), "+f"(c[1]), "+f"(c[2]), "+f"(c[3])
        : "r"(a[0]), "r"(a[1]), "r"(a[2]), "r"(a[3]), "r"(b[0]), "r"(b[1]));
}

// ---------------- packing / convert kernels ----------------
__global__ void pack_b1(const float* __restrict__ R,  const float* __restrict__ Rb,
                        const float* __restrict__ Kw, const float* __restrict__ Kb,
                        const float* __restrict__ Vw, const float* __restrict__ Vb,
                        const float* __restrict__ w1, const float* __restrict__ a1,
                        const float* __restrict__ v1)
{
    size_t idx = (size_t)blockIdx.x*blockDim.x + threadIdx.x;
    if (idx < N1) {
        float bv = 0.f;
        if (idx < 2048) bv = Rb[idx];
        else if (idx < 2560) bv = Kb[idx-2048];
        else if (idx < 3072) bv = Vb[idx-2560];
        g_bias1[idx] = bv;
    }
    if (idx >= (size_t)N1*CC) return;
    int n = (int)(idx / CC), k = (int)(idx % CC);
    float v = 0.f;
    if      (n < 2048) v = R [(size_t)n*CC + k];
    else if (n < 2560) v = Kw[(size_t)(n-2048)*CC + k];
    else if (n < 3072) v = Vw[(size_t)(n-2560)*CC + k];
    else if (n < 3136) v = w1[(size_t)k*64 + (n-3072)];
    else if (n < 3200) v = a1[(size_t)k*64 + (n-3136)];
    else if (n < 3232) v = v1[(size_t)k*32 + (n-3200)];
    split2h(v, &g_b1hi[idx], &g_b1lo[idx]);
}

__global__ void pack_b2(const float* __restrict__ w2, const float* __restrict__ a2,
                        const float* __restrict__ v2)
{
    int idx = blockIdx.x*blockDim.x + threadIdx.x;
    if (idx >= CC*64) return;
    int n = idx / 64, k = idx % 64;
    split2h(w2[(size_t)k*CC + n], &g_w2hi[idx], &g_w2lo[idx]);
    split2h(a2[(size_t)k*CC + n], &g_a2hi[idx], &g_a2lo[idx]);
    float vv = (k < 32) ? v2[(size_t)k*CC + n] : 0.f;
    split2h(vv, &g_v2hi[idx], &g_v2lo[idx]);
}

__global__ void split_o(const float* __restrict__ src)
{
    size_t i = (size_t)blockIdx.x*blockDim.x + threadIdx.x;
    if (i < (size_t)CC*CC) split2h(src[i], &g_ohi[i], &g_olo[i]);
}

__global__ void cvt_h(const float* __restrict__ src, __half* __restrict__ dst, size_t n4)
{
    size_t i = (size_t)blockIdx.x*blockDim.x + threadIdx.x;
    if (i >= n4) return;
    float4 v = *(const float4*)(src + i*4);
    __half h[4] = {__float2half_rn(v.x), __float2half_rn(v.y),
                   __float2half_rn(v.z), __float2half_rn(v.w)};
    *(uint2*)(dst + i*4) = *(uint2*)h;
}

__global__ void hid_cvt()
{
    size_t idx = (size_t)blockIdx.x*blockDim.x + threadIdx.x;
    if (idx >= (size_t)MM*HIDP) return;
    int m = (int)(idx / HIDP), j = (int)(idx % HIDP);
    const float* row = g_proj + (size_t)m*N1 + 3072;
    float v = 0.f;
    if (j < 64)       v = tanhf(row[j]);
    else if (j < 160) v = row[j];
    g_hidh[idx] = __float2half_rn(v);
}

// ---------------- fp16 2-product HMMA NT GEMM: C = Ah*(Bhi+Blo)^T + bias --------
// BM=BN=128, BK=32, 256 threads (8 warps, warp tile 64x32), cp.async double buffer.
#define SPAD 40                     // smem row stride in fp16 elems (32 + 8 pad)
#define TILEB (128*SPAD*2)          // 10240 B per operand tile
#define STAGEB (3*TILEB)            // 30720 B per stage (A, Bhi, Blo)

__global__ void __launch_bounds__(256,2) hmma_nt(
    const __half* __restrict__ Ah, int lda,
    const __half* __restrict__ Bhi, const __half* __restrict__ Blo, int ldb,
    const float* __restrict__ bias, float* __restrict__ Cc, int ldc, int KT)
{
    extern __shared__ __align__(128) char smem[];
    const int tid  = threadIdx.x;
    const int warp = tid >> 5;
    const int lane = tid & 31;
    const int bm   = blockIdx.y * 128;
    const int bn   = blockIdx.x * 128;
    const int wm   = (warp & 1) * 64;   // warp row base within block
    const int wn   = (warp >> 1) * 32;  // warp col base within block

    float acc[4][4][4];
    #pragma unroll
    for (int a=0;a<4;a++)
        #pragma unroll
        for (int b=0;b<4;b++)
            #pragma unroll
            for (int c=0;c<4;c++) acc[a][b][c]=0.f;

    auto load_stage = [&](int stage, int kt){
        const int k0 = kt * 32;
        char* sb = smem + stage * STAGEB;
        const __half* bases[3];
        int lds[3];
        bases[0] = Ah  + (size_t)bm*lda + k0; lds[0] = lda;
        bases[1] = Bhi + (size_t)bn*ldb + k0; lds[1] = ldb;
        bases[2] = Blo + (size_t)bn*ldb + k0; lds[2] = ldb;
        #pragma unroll
        for (int t = 0; t < 3; t++){
            #pragma unroll
            for (int it = 0; it < 2; it++){
                int idx = it*256 + tid;         // 0..511
                int r = idx >> 2, c = idx & 3;  // row, 16B chunk
                cp_async16(sb + t*TILEB + (r*SPAD + c*8)*2,
                           bases[t] + (size_t)r*lds[t] + c*8);
            }
        }
        asm volatile("cp.async.commit_group;" ::: "memory");
    };

    load_stage(0, 0);

    const uint32_t sbase = (uint32_t)__cvta_generic_to_shared(smem);

    for (int kt = 0; kt < KT; kt++){
        const int buf = kt & 1;
        if (kt + 1 < KT){
            load_stage(buf ^ 1, kt + 1);
            asm volatile("cp.async.wait_group 1;" ::: "memory");
        } else {
            asm volatile("cp.async.wait_group 0;" ::: "memory");
        }
        __syncthreads();

        const uint32_t sA    = sbase + buf*STAGEB;
        const uint32_t sB_hi = sA + TILEB;
        const uint32_t sB_lo = sA + 2*TILEB;

        #pragma unroll
        for (int ks = 0; ks < 2; ks++){
            uint32_t aF[4][4], bH[2][4], bL[2][4];
            // B fragments: one x4 covers 2 n-frags (n16 x k16)
            #pragma unroll
            for (int half = 0; half < 2; half++){
                int nrow = wn + half*16 + (lane & 7) + ((lane >> 4) << 3);
                int ncol = ks*16 + ((lane >> 3) & 1)*8;
                uint32_t off = (uint32_t)(nrow*SPAD + ncol)*2;
                ldsm4(bH[half], sB_hi + off);
                ldsm4(bL[half], sB_lo + off);
            }
            // A fragments
            #pragma unroll
            for (int mf = 0; mf < 4; mf++){
                int arow = wm + mf*16 + (lane & 15);
                int acol = ks*16 + (lane >> 4)*8;
                ldsm4(aF[mf], sA + (uint32_t)(arow*SPAD + acol)*2);
            }
            #pragma unroll
            for (int mf = 0; mf < 4; mf++)
                #pragma unroll
                for (int nf = 0; nf < 4; nf++){
                    mma16816(acc[mf][nf], aF[mf], &bH[nf>>1][(nf&1)*2]);
                    mma16816(acc[mf][nf], aF[mf], &bL[nf>>1][(nf&1)*2]);
                }
        }
        __syncthreads();
    }

    // epilogue
    #pragma unroll
    for (int mf = 0; mf < 4; mf++){
        #pragma unroll
        for (int nf = 0; nf < 4; nf++){
            int row0 = bm + wm + mf*16 + (lane >> 2);
            int col0 = bn + wn + nf*8  + (lane & 3)*2;
            float b0 = 0.f, b1 = 0.f;
            if (bias){ b0 = bias[col0]; b1 = bias[col0+1]; }
            float2 v0 = make_float2(acc[mf][nf][0] + b0, acc[mf][nf][1] + b1);
            float2 v1 = make_float2(acc[mf][nf][2] + b0, acc[mf][nf][3] + b1);
            *(float2*)(Cc + (size_t)row0*ldc + col0)       = v0;
            *(float2*)(Cc + (size_t)(row0+8)*ldc + col0)   = v1;
        }
    }
}

// ---------------- prep: gates, decay, kk norm, pack scan inputs ----------------
__global__ void __launch_bounds__(512) prep_kernel(
        const float* __restrict__ vfirst,
        const float* __restrict__ w0, const float* __restrict__ a0, const float* __restrict__ v0,
        const float* __restrict__ k_k, const float* __restrict__ k_a, const float* __restrict__ r_k)
{
    int m = blockIdx.x;
    int b = m / TT, t = m % TT;
    int tid = threadIdx.x;
    int j0 = tid * 4;
    int h  = j0 >> 6;
    int kvidx = (h >> 2)*64 + (j0 & 63);

    const float* prow = g_proj + (size_t)m*N1;
    float4 rv = *(const float4*)(prow + j0);
    float4 kp = *(const float4*)(prow + 2048 + kvidx);
    float4 vp = *(const float4*)(prow + 2560 + kvidx);
    float4 wt = *(const float4*)(g_wterm + (size_t)m*CC + j0);
    float4 at = *(const float4*)(g_aterm + (size_t)m*CC + j0);
    float4 vt = *(const float4*)(g_vterm + (size_t)m*CC + j0);
    float4 vf = *(const float4*)(vfirst + (size_t)m*CC + j0);
    float4 kkw = *(const float4*)(k_k + j0);
    float4 kaw = *(const float4*)(k_a + j0);
    float4 rkw = *(const float4*)(r_k + j0);
    float4 w0v = *(const float4*)(w0 + j0);
    float4 a0v = *(const float4*)(a0 + j0);
    float4 v0v = *(const float4*)(v0 + j0);

    float rr[4]  = {rv.x, rv.y, rv.z, rv.w};
    float kpv[4] = {kp.x, kp.y, kp.z, kp.w};
    float vpv[4] = {vp.x, vp.y, vp.z, vp.w};
    float wtv[4] = {wt.x, wt.y, wt.z, wt.w};
    float atv[4] = {at.x, at.y, at.z, at.w};
    float vtv[4] = {vt.x, vt.y, vt.z, vt.w};
    float vfv[4] = {vf.x, vf.y, vf.z, vf.w};
    float kkwv[4]= {kkw.x,kkw.y,kkw.z,kkw.w};
    float kawv[4]= {kaw.x,kaw.y,kaw.z,kaw.w};
    float rkv[4] = {rkw.x,rkw.y,rkw.z,rkw.w};
    float w0a[4] = {w0v.x,w0v.y,w0v.z,w0v.w};
    float a0a[4] = {a0v.x,a0v.y,a0v.z,a0v.w};
    float v0a[4] = {v0v.x,v0v.y,v0v.z,v0v.w};

    float aga[4], dec[4], kkpre[4], kmod[4], vb[4];
    float nrm = 0.f;
    #pragma unroll
    for (int c=0;c<4;c++){
        float u = w0a[c] + wtv[c];
        float z = -u;
        float sp = (z > 20.f) ? z : log1pf(expf(z));
        float wraw = -sp - 0.6f;
        dec[c] = expf(-expf(wraw));
        float a = sigmoidf_(a0a[c] + atv[c]);
        aga[c] = a;
        kkpre[c] = kpv[c] * kkwv[c];
        nrm += kkpre[c]*kkpre[c];
        kmod[c] = kpv[c] * (1.f + (a - 1.f) * kawv[c]);
        float vsel = sigmoidf_(v0a[c] + vtv[c]);
        vb[c] = vpv[c] + (vfv[c] - vpv[c]) * vsel;
    }
    float tot = redux16(nrm);
    float inv = 1.f / fmaxf(sqrtf(tot), 1e-12f);

    float aav[4], bbv[4];
    float dsum = 0.f;
    #pragma unroll
    for (int c=0;c<4;c++){
        float kkn = kkpre[c]*inv;
        aav[c] = -kkn;
        bbv[c] = kkn*aga[c];
        dsum += rr[c]*kmod[c]*rkv[c];
    }
    float dtot = redux16(dsum);
    if ((tid & 15) == 0) g_bcoef[(size_t)m*HH + h] = dtot;

    size_t base = ((size_t)(b*HH + h)*TT + t)*384 + (j0 & 63);
    *(float4*)(g_packed + base +   0) = rv;
    *(float4*)(g_packed + base +  64) = make_float4(dec[0],dec[1],dec[2],dec[3]);
    *(float4*)(g_packed + base + 128) = make_float4(kmod[0],kmod[1],kmod[2],kmod[3]);
    *(float4*)(g_packed + base + 192) = make_float4(vb[0],vb[1],vb[2],vb[3]);
    *(float4*)(g_packed + base + 256) = make_float4(aav[0],aav[1],aav[2],aav[3]);
    *(float4*)(g_packed + base + 320) = make_float4(bbv[0],bbv[1],bbv[2],bbv[3]);
}

// ---------------- recurrent scan: one block per (b,h) ----------------
__global__ void __launch_bounds__(256,1) scan_kernel(const float* __restrict__ state0)
{
    __shared__ float buf[4][384];
    __shared__ float redA[64], redB[64];
    const int bh = blockIdx.x;
    const int tid = threadIdx.x;
    const int i = tid >> 2;
    const int q = tid & 3;
    const int kb = q * 16;

    float S[16];
    #pragma unroll
    for (int c=0;c<16;c++)
        S[c] = state0[((size_t)bh*64 + i)*64 + kb + c];

    const float* src = g_packed + (size_t)bh*TT*384;

    if (tid < 96) {
        #pragma unroll
        for (int s=0;s<4;s++){
            cp_async16(&buf[s][tid*4], src + (size_t)s*384 + tid*4);
            asm volatile("cp.async.commit_group;\n");
        }
    }

    const int b = bh >> 5, h = bh & 31;
    float* yout = g_y + ((size_t)b*TT*HH + h)*NNd + i;
    float gsum = 0.f, gsq = 0.f;

    for (int t = 0; t < TT; t++) {
        if (tid < 96) asm volatile("cp.async.wait_group 3;\n");
        __syncthreads();
        const float* vbuf = buf[t & 3];

        float rr[16], dd[16], km[16], av[16], bv[16];
        #pragma unroll
        for (int m4=0;m4<4;m4++){
            float4 x0 = *(const float4*)&vbuf[  0 + kb + m4*4];
            float4 x1 = *(const float4*)&vbuf[ 64 + kb + m4*4];
            float4 x2 = *(const float4*)&vbuf[128 + kb + m4*4];
            float4 x4 = *(const float4*)&vbuf[256 + kb + m4*4];
            float4 x5 = *(const float4*)&vbuf[320 + kb + m4*4];
            rr[m4*4+0]=x0.x; rr[m4*4+1]=x0.y; rr[m4*4+2]=x0.z; rr[m4*4+3]=x0.w;
            dd[m4*4+0]=x1.x; dd[m4*4+1]=x1.y; dd[m4*4+2]=x1.z; dd[m4*4+3]=x1.w;
            km[m4*4+0]=x2.x; km[m4*4+1]=x2.y; km[m4*4+2]=x2.z; km[m4*4+3]=x2.w;
            av[m4*4+0]=x4.x; av[m4*4+1]=x4.y; av[m4*4+2]=x4.z; av[m4*4+3]=x4.w;
            bv[m4*4+0]=x5.x; bv[m4*4+1]=x5.y; bv[m4*4+2]=x5.z; bv[m4*4+3]=x5.w;
        }
        float vi = vbuf[192 + i];

        float sa = 0.f;
        #pragma unroll
        for (int c=0;c<16;c++) sa += S[c]*av[c];
        sa += __shfl_xor_sync(0xffffffffu, sa, 1);
        sa += __shfl_xor_sync(0xffffffffu, sa, 2);

        float yp = 0.f;
        #pragma unroll
        for (int c=0;c<16;c++){
            S[c] = S[c]*dd[c] + sa*bv[c] + vi*km[c];
            yp += S[c]*rr[c];
        }
        yp += __shfl_xor_sync(0xffffffffu, yp, 1);
        yp += __shfl_xor_sync(0xffffffffu, yp, 2);

        if (q == 0) {
            yout[(size_t)t*CC] = yp;
            gsum += yp; gsq += yp*yp;
        }
        __syncthreads();
        if (tid < 96) {
            int tt = (t+4 < TT) ? (t+4) : (TT-1);
            cp_async16(&buf[(t+4)&3][tid*4], src + (size_t)tt*384 + tid*4);
            asm volatile("cp.async.commit_group;\n");
        }
    }

    if (q == 0) { redA[i] = gsum; redB[i] = gsq; }
    __syncthreads();
    if (tid < 32) {
        float s1 = redA[tid] + redA[tid+32];
        float s2 = redB[tid] + redB[tid+32];
        #pragma unroll
        for (int off=16; off>=1; off>>=1){
            s1 += __shfl_xor_sync(0xffffffffu, s1, off);
            s2 += __shfl_xor_sync(0xffffffffu, s2, off);
        }
        if (tid == 0) {
            float cnt = (float)(TT*NNd);
            float mean = s1 / cnt;
            float var  = s2 / cnt - mean*mean;
            g_gn[bh*2]   = mean;
            g_gn[bh*2+1] = rsqrtf(var + 0.00064f);
        }
    }
}

// ---------------- groupnorm apply + bonus, fused fp16 convert ----------------
__global__ void __launch_bounds__(512) apply_kernel(
        const float* __restrict__ ln_w, const float* __restrict__ ln_b)
{
    int m = blockIdx.x;
    int b = m / TT, t = m % TT;
    int tid = threadIdx.x;
    int j0 = tid * 4;
    int h = j0 >> 6;

    float mean = g_gn[(b*HH + h)*2];
    float rstd = g_gn[(b*HH + h)*2 + 1];
    float bc   = g_bcoef[(size_t)m*HH + h];

    float4 yv = *(const float4*)(g_y + (size_t)m*CC + j0);
    float4 lw = *(const float4*)(ln_w + j0);
    float4 lb = *(const float4*)(ln_b + j0);
    size_t pbase = ((size_t)(b*HH + h)*TT + t)*384 + (j0 & 63);
    float4 vb = *(const float4*)(g_packed + pbase + 192);

    float o[4];
    o[0] = (yv.x - mean)*rstd*lw.x + lb.x + bc*vb.x;
    o[1] = (yv.y - mean)*rstd*lw.y + lb.y + bc*vb.y;
    o[2] = (yv.z - mean)*rstd*lw.z + lb.z + bc*vb.z;
    o[3] = (yv.w - mean)*rstd*lw.w + lb.w + bc*vb.w;

    __half hv[4];
    #pragma unroll
    for (int c=0;c<4;c++) hv[c] = __float2half_rn(o[c]);
    *(uint2*)(g_xxh + (size_t)m*CC + j0) = *(uint2*)hv;
}

// ---------------- launch ----------------
extern "C" void kernel_launch(void* const* d_in, const int* in_sizes, int n_in,
                              void* d_out, int out_size)
{
    const float* x      = (const float*)d_in[0];
    const float* vfirst = (const float*)d_in[1];
    const float* state  = (const float*)d_in[2];
    const float* Rw     = (const float*)d_in[3];
    const float* Rb     = (const float*)d_in[4];
    const float* Kw     = (const float*)d_in[5];
    const float* Kb     = (const float*)d_in[6];
    const float* Vw     = (const float*)d_in[7];
    const float* Vb     = (const float*)d_in[8];
    const float* Ow     = (const float*)d_in[9];
    const float* Ob     = (const float*)d_in[10];
    const float* w0     = (const float*)d_in[11];
    const float* w1     = (const float*)d_in[12];
    const float* w2     = (const float*)d_in[13];
    const float* a0     = (const float*)d_in[14];
    const float* a1     = (const float*)d_in[15];
    const float* a2     = (const float*)d_in[16];
    const float* v0     = (const float*)d_in[17];
    const float* v1     = (const float*)d_in[18];
    const float* v2     = (const float*)d_in[19];
    const float* k_k    = (const float*)d_in[20];
    const float* k_a    = (const float*)d_in[21];
    const float* r_k    = (const float*)d_in[22];
    const float* ln_w   = (const float*)d_in[23];
    const float* ln_b   = (const float*)d_in[24];
    float* out = (float*)d_out;

    cudaFuncSetAttribute(hmma_nt, cudaFuncAttributeMaxDynamicSharedMemorySize, 2*STAGEB);

    float *proj, *wterm, *aterm, *vterm, *bias1;
    __half *xh, *b1hi, *b1lo, *hh;
    __half *w2hi, *w2lo, *a2hi, *a2lo, *v2hi, *v2lo;
    __half *xxh, *ohi, *olo;
    cudaGetSymbolAddress((void**)&proj,  g_proj);
    cudaGetSymbolAddress((void**)&wterm, g_wterm);
    cudaGetSymbolAddress((void**)&aterm, g_aterm);
    cudaGetSymbolAddress((void**)&vterm, g_vterm);
    cudaGetSymbolAddress((void**)&bias1, g_bias1);
    cudaGetSymbolAddress((void**)&xh,    g_xh);
    cudaGetSymbolAddress((void**)&b1hi,  g_b1hi);
    cudaGetSymbolAddress((void**)&b1lo,  g_b1lo);
    cudaGetSymbolAddress((void**)&hh,    g_hidh);
    cudaGetSymbolAddress((void**)&w2hi,  g_w2hi);
    cudaGetSymbolAddress((void**)&w2lo,  g_w2lo);
    cudaGetSymbolAddress((void**)&a2hi,  g_a2hi);
    cudaGetSymbolAddress((void**)&a2lo,  g_a2lo);
    cudaGetSymbolAddress((void**)&v2hi,  g_v2hi);
    cudaGetSymbolAddress((void**)&v2lo,  g_v2lo);
    cudaGetSymbolAddress((void**)&xxh,   g_xxh);
    cudaGetSymbolAddress((void**)&ohi,   g_ohi);
    cudaGetSymbolAddress((void**)&olo,   g_olo);

    // weight packing (hi+lo) + activation convert (hi only)
    pack_b1<<<(int)(((size_t)N1*CC + 255)/256), 256>>>(Rw, Rb, Kw, Kb, Vw, Vb, w1, a1, v1);
    pack_b2<<<(CC*64 + 255)/256, 256>>>(w2, a2, v2);
    split_o<<<(int)(((size_t)CC*CC + 255)/256), 256>>>(Ow);
    cvt_h<<<(int)(((size_t)MM*CC/4 + 255)/256), 256>>>(x, xh, (size_t)MM*CC/4);

    // GEMM1: proj = x @ [R|K|V|w1|a1|v1]^T + bias1   (M=4096, N=3328, K=2048)
    {
        dim3 g(N1/128, MM/128);
        hmma_nt<<<g, 256, 2*STAGEB>>>(xh, CC, b1hi, b1lo, CC, bias1, proj, N1, CC/32);
    }
    hid_cvt<<<(int)(((size_t)MM*HIDP + 255)/256), 256>>>();

    // stage-2 small-K GEMMs (K=64 -> KT=2)
    {
        dim3 g(CC/128, MM/128);
        hmma_nt<<<g, 256, 2*STAGEB>>>(hh,       HIDP, w2hi, w2lo, 64, nullptr, wterm, CC, 2);
        hmma_nt<<<g, 256, 2*STAGEB>>>(hh + 64,  HIDP, a2hi, a2lo, 64, nullptr, aterm, CC, 2);
        hmma_nt<<<g, 256, 2*STAGEB>>>(hh + 128, HIDP, v2hi, v2lo, 64, nullptr, vterm, CC, 2);
    }

    prep_kernel<<<MM, 512>>>(vfirst, w0, a0, v0, k_k, k_a, r_k);
    scan_kernel<<<BB*HH, 256>>>(state);
    apply_kernel<<<MM, 512>>>(ln_w, ln_b);

    // out = xx @ O^T + O_bias   (M=4096, N=2048, K=2048)
    {
        dim3 g(CC/128, MM/128);
        hmma_nt<<<g, 256, 2*STAGEB>>>(xxh, CC, ohi, olo, CC, Ob, out, CC, CC/32);
    }
}

// round 10
// speedup vs baseline: 2.7547x; 1.0060x over previous
#include <cuda_runtime.h>
#include <cuda_fp16.h>
#include <math.h>
#include <stdint.h>

#define BB 4
#define TT 1024
#define CC 2048
#define HH 32
#define NNd 64
#define KVD 512
#define MM (BB*TT)      // 4096 tokens
#define N1 3328         // combined GEMM1 N: 2048(R)+512(K)+512(V)+160(lora)+96 pad
#define HIDP 192        // hidden padded cols

// ---------------- scratch (static device arrays; no allocation) ----------------
__device__ __align__(128) __half g_xh[(size_t)MM*CC];
__device__ __align__(128) __half g_b1hi[(size_t)N1*CC];
__device__ __align__(128) __half g_b1lo[(size_t)N1*CC];
__device__ __align__(128) float g_bias1[N1];
__device__ __align__(128) float g_proj[(size_t)MM*N1];
__device__ __align__(128) __half g_hidh[(size_t)MM*HIDP];
__device__ __align__(128) __half g_w2hi[CC*64];
__device__ __align__(128) __half g_w2lo[CC*64];
__device__ __align__(128) __half g_a2hi[CC*64];
__device__ __align__(128) __half g_a2lo[CC*64];
__device__ __align__(128) __half g_v2hi[CC*64];
__device__ __align__(128) __half g_v2lo[CC*64];
__device__ __align__(128) float g_wterm[(size_t)MM*CC];
__device__ __align__(128) float g_aterm[(size_t)MM*CC];
__device__ __align__(128) float g_vterm[(size_t)MM*CC];
__device__ __align__(128) float g_packed[(size_t)BB*HH*TT*384];
__device__ __align__(128) float g_y[(size_t)MM*CC];
__device__ __align__(128) __half g_xxh[(size_t)MM*CC];
__device__ __align__(128) __half g_ohi[(size_t)CC*CC];
__device__ __align__(128) __half g_olo[(size_t)CC*CC];
__device__ __align__(128) float g_bcoef[(size_t)MM*HH];
__device__ __align__(128) float g_gn[BB*HH*2];

// ---------------- helpers ----------------
__device__ __forceinline__ float sigmoidf_(float x){ return 1.0f/(1.0f + expf(-x)); }

__device__ __forceinline__ float redux16(float v){
    v += __shfl_xor_sync(0xffffffffu, v, 1);
    v += __shfl_xor_sync(0xffffffffu, v, 2);
    v += __shfl_xor_sync(0xffffffffu, v, 4);
    v += __shfl_xor_sync(0xffffffffu, v, 8);
    return v;
}

__device__ __forceinline__ void cp_async16(void* smem, const void* gmem){
    unsigned s = (unsigned)__cvta_generic_to_shared(smem);
    asm volatile("cp.async.cg.shared.global [%0], [%1], 16;\n" :: "r"(s), "l"(gmem));
}

__device__ __forceinline__ void split2h(float v, __half* hi, __half* lo){
    __half h = __float2half_rn(v);
    *hi = h;
    *lo = __float2half_rn(v - __half2float(h));
}

// ---------------- mma.sync helpers (legacy tensor path; plain sm_103 target) ----
__device__ __forceinline__ void ldsm4(uint32_t* r, uint32_t addr){
    asm volatile("ldmatrix.sync.aligned.m8n8.x4.shared.b16 {%0,%1,%2,%3}, [%4];"
                 : "=r"(r[0]), "=r"(r[1]), "=r"(r[2]), "=r"(r[3]) : "r"(addr));
}

__device__ __forceinline__ void mma16816(float* c, const uint32_t* a, const uint32_t* b){
    asm volatile(
        "mma.sync.aligned.m16n8k16.row.col.f32.f16.f16.f32 "
        "{%0,%1,%2,%3}, {%4,%5,%6,%7}, {%8,%9}, {%0,%1,%2,%3};"
        : "+f"(c[0]), "+f"(c[1]), "+f"(c[2]), "+f"(c[3])
        : "r"(a[0]), "r"(a[1]), "r"(a[2]), "r"(a[3]), "r"(b[0]), "r"(b[1]));
}

// ---------------- packing / convert kernels ----------------
__global__ void pack_b1(const float* __restrict__ R,  const float* __restrict__ Rb,
                        const float* __restrict__ Kw, const float* __restrict__ Kb,
                        const float* __restrict__ Vw, const float* __restrict__ Vb,
                        const float* __restrict__ w1, const float* __restrict__ a1,
                        const float* __restrict__ v1)
{
    size_t idx = (size_t)blockIdx.x*blockDim.x + threadIdx.x;
    if (idx < N1) {
        float bv = 0.f;
        if (idx < 2048) bv = Rb[idx];
        else if (idx < 2560) bv = Kb[idx-2048];
        else if (idx < 3072) bv = Vb[idx-2560];
        g_bias1[idx] = bv;
    }
    if (idx >= (size_t)N1*CC) return;
    int n = (int)(idx / CC), k = (int)(idx % CC);
    float v = 0.f;
    if      (n < 2048) v = R [(size_t)n*CC + k];
    else if (n < 2560) v = Kw[(size_t)(n-2048)*CC + k];
    else if (n < 3072) v = Vw[(size_t)(n-2560)*CC + k];
    else if (n < 3136) v = w1[(size_t)k*64 + (n-3072)];
    else if (n < 3200) v = a1[(size_t)k*64 + (n-3136)];
    else if (n < 3232) v = v1[(size_t)k*32 + (n-3200)];
    split2h(v, &g_b1hi[idx], &g_b1lo[idx]);
}

__global__ void pack_b2(const float* __restrict__ w2, const float* __restrict__ a2,
                        const float* __restrict__ v2)
{
    int idx = blockIdx.x*blockDim.x + threadIdx.x;
    if (idx >= CC*64) return;
    int n = idx / 64, k = idx % 64;
    split2h(w2[(size_t)k*CC + n], &g_w2hi[idx], &g_w2lo[idx]);
    split2h(a2[(size_t)k*CC + n], &g_a2hi[idx], &g_a2lo[idx]);
    float vv = (k < 32) ? v2[(size_t)k*CC + n] : 0.f;
    split2h(vv, &g_v2hi[idx], &g_v2lo[idx]);
}

// merged: split Ow into hi/lo AND convert x to fp16 (keeps GEMM1 as 4th launch)
__global__ void split_ox(const float* __restrict__ Ow, const float* __restrict__ x)
{
    size_t stride = (size_t)gridDim.x * blockDim.x;
    size_t i0 = (size_t)blockIdx.x*blockDim.x + threadIdx.x;
    for (size_t i = i0; i < (size_t)CC*CC; i += stride)
        split2h(Ow[i], &g_ohi[i], &g_olo[i]);
    for (size_t i = i0; i < (size_t)MM*CC/4; i += stride){
        float4 v = *(const float4*)(x + i*4);
        __half h[4] = {__float2half_rn(v.x), __float2half_rn(v.y),
                       __float2half_rn(v.z), __float2half_rn(v.w)};
        *(uint2*)(g_xh + i*4) = *(uint2*)h;
    }
}

__global__ void hid_cvt()
{
    size_t idx = (size_t)blockIdx.x*blockDim.x + threadIdx.x;
    if (idx >= (size_t)MM*HIDP) return;
    int m = (int)(idx / HIDP), j = (int)(idx % HIDP);
    const float* row = g_proj + (size_t)m*N1 + 3072;
    float v = 0.f;
    if (j < 64)       v = tanhf(row[j]);
    else if (j < 160) v = row[j];
    g_hidh[idx] = __float2half_rn(v);
}

// ---------------- fp16 2-product HMMA NT GEMM: C = Ah*(Bhi+Blo)^T + bias --------
// BM=BN=128, BK=32, 256 threads (8 warps, warp tile 64x32).
// 3-stage cp.async ring, ONE __syncthreads per K-tile.
#define SPAD 40                     // smem row stride in fp16 elems (32 + 8 pad)
#define TILEB (128*SPAD*2)          // 10240 B per operand tile
#define STAGEB (3*TILEB)            // 30720 B per stage (A, Bhi, Blo)
#define NSTAGE 3

__global__ void __launch_bounds__(256,2) hmma_nt(
    const __half* __restrict__ Ah, int lda,
    const __half* __restrict__ Bhi, const __half* __restrict__ Blo, int ldb,
    const float* __restrict__ bias, float* __restrict__ Cc, int ldc, int KT)
{
    extern __shared__ __align__(128) char smem[];
    const int tid  = threadIdx.x;
    const int warp = tid >> 5;
    const int lane = tid & 31;
    const int bm   = blockIdx.y * 128;
    const int bn   = blockIdx.x * 128;
    const int wm   = (warp & 1) * 64;   // warp row base within block
    const int wn   = (warp >> 1) * 32;  // warp col base within block

    float acc[4][4][4];
    #pragma unroll
    for (int a=0;a<4;a++)
        #pragma unroll
        for (int b=0;b<4;b++)
            #pragma unroll
            for (int c=0;c<4;c++) acc[a][b][c]=0.f;

    auto load_stage = [&](int stage, int kt){
        const int k0 = kt * 32;
        char* sb = smem + stage * STAGEB;
        const __half* bases[3];
        int lds[3];
        bases[0] = Ah  + (size_t)bm*lda + k0; lds[0] = lda;
        bases[1] = Bhi + (size_t)bn*ldb + k0; lds[1] = ldb;
        bases[2] = Blo + (size_t)bn*ldb + k0; lds[2] = ldb;
        #pragma unroll
        for (int t = 0; t < 3; t++){
            #pragma unroll
            for (int it = 0; it < 2; it++){
                int idx = it*256 + tid;         // 0..511
                int r = idx >> 2, c = idx & 3;  // row, 16B chunk
                cp_async16(sb + t*TILEB + (r*SPAD + c*8)*2,
                           bases[t] + (size_t)r*lds[t] + c*8);
            }
        }
        asm volatile("cp.async.commit_group;" ::: "memory");
    };

    // prologue: stages 0,1
    load_stage(0, 0);
    if (KT > 1) load_stage(1, 1);

    const uint32_t sbase = (uint32_t)__cvta_generic_to_shared(smem);

    for (int kt = 0; kt < KT; kt++){
        const int buf = kt % NSTAGE;
        if (kt + 1 < KT) asm volatile("cp.async.wait_group 1;" ::: "memory");
        else             asm volatile("cp.async.wait_group 0;" ::: "memory");
        __syncthreads();
        // prefetch kt+2 into (kt+2)%3 == (kt-1)%3 — safe: the barrier above proves
        // every warp finished computing stage kt-1.
        if (kt + 2 < KT) load_stage((kt + 2) % NSTAGE, kt + 2);

        const uint32_t sA    = sbase + buf*STAGEB;
        const uint32_t sB_hi = sA + TILEB;
        const uint32_t sB_lo = sA + 2*TILEB;

        #pragma unroll
        for (int ks = 0; ks < 2; ks++){
            uint32_t aF[4][4], bH[2][4], bL[2][4];
            // B fragments: one x4 covers 2 n-frags (n16 x k16)
            #pragma unroll
            for (int half = 0; half < 2; half++){
                int nrow = wn + half*16 + (lane & 7) + ((lane >> 4) << 3);
                int ncol = ks*16 + ((lane >> 3) & 1)*8;
                uint32_t off = (uint32_t)(nrow*SPAD + ncol)*2;
                ldsm4(bH[half], sB_hi + off);
                ldsm4(bL[half], sB_lo + off);
            }
            // A fragments
            #pragma unroll
            for (int mf = 0; mf < 4; mf++){
                int arow = wm + mf*16 + (lane & 15);
                int acol = ks*16 + (lane >> 4)*8;
                ldsm4(aF[mf], sA + (uint32_t)(arow*SPAD + acol)*2);
            }
            #pragma unroll
            for (int mf = 0; mf < 4; mf++)
                #pragma unroll
                for (int nf = 0; nf < 4; nf++){
                    mma16816(acc[mf][nf], aF[mf], &bH[nf>>1][(nf&1)*2]);
                    mma16816(acc[mf][nf], aF[mf], &bL[nf>>1][(nf&1)*2]);
                }
        }
    }

    // epilogue
    #pragma unroll
    for (int mf = 0; mf < 4; mf++){
        #pragma unroll
        for (int nf = 0; nf < 4; nf++){
            int row0 = bm + wm + mf*16 + (lane >> 2);
            int col0 = bn + wn + nf*8  + (lane & 3)*2;
            float b0 = 0.f, b1 = 0.f;
            if (bias){ b0 = bias[col0]; b1 = bias[col0+1]; }
            float2 v0 = make_float2(acc[mf][nf][0] + b0, acc[mf][nf][1] + b1);
            float2 v1 = make_float2(acc[mf][nf][2] + b0, acc[mf][nf][3] + b1);
            *(float2*)(Cc + (size_t)row0*ldc + col0)       = v0;
            *(float2*)(Cc + (size_t)(row0+8)*ldc + col0)   = v1;
        }
    }
}

// ---------------- prep: gates, decay, kk norm, pack scan inputs ----------------
__global__ void __launch_bounds__(512) prep_kernel(
        const float* __restrict__ vfirst,
        const float* __restrict__ w0, const float* __restrict__ a0, const float* __restrict__ v0,
        const float* __restrict__ k_k, const float* __restrict__ k_a, const float* __restrict__ r_k)
{
    int m = blockIdx.x;
    int b = m / TT, t = m % TT;
    int tid = threadIdx.x;
    int j0 = tid * 4;
    int h  = j0 >> 6;
    int kvidx = (h >> 2)*64 + (j0 & 63);

    const float* prow = g_proj + (size_t)m*N1;
    float4 rv = *(const float4*)(prow + j0);
    float4 kp = *(const float4*)(prow + 2048 + kvidx);
    float4 vp = *(const float4*)(prow + 2560 + kvidx);
    float4 wt = *(const float4*)(g_wterm + (size_t)m*CC + j0);
    float4 at = *(const float4*)(g_aterm + (size_t)m*CC + j0);
    float4 vt = *(const float4*)(g_vterm + (size_t)m*CC + j0);
    float4 vf = *(const float4*)(vfirst + (size_t)m*CC + j0);
    float4 kkw = *(const float4*)(k_k + j0);
    float4 kaw = *(const float4*)(k_a + j0);
    float4 rkw = *(const float4*)(r_k + j0);
    float4 w0v = *(const float4*)(w0 + j0);
    float4 a0v = *(const float4*)(a0 + j0);
    float4 v0v = *(const float4*)(v0 + j0);

    float rr[4]  = {rv.x, rv.y, rv.z, rv.w};
    float kpv[4] = {kp.x, kp.y, kp.z, kp.w};
    float vpv[4] = {vp.x, vp.y, vp.z, vp.w};
    float wtv[4] = {wt.x, wt.y, wt.z, wt.w};
    float atv[4] = {at.x, at.y, at.z, at.w};
    float vtv[4] = {vt.x, vt.y, vt.z, vt.w};
    float vfv[4] = {vf.x, vf.y, vf.z, vf.w};
    float kkwv[4]= {kkw.x,kkw.y,kkw.z,kkw.w};
    float kawv[4]= {kaw.x,kaw.y,kaw.z,kaw.w};
    float rkv[4] = {rkw.x,rkw.y,rkw.z,rkw.w};
    float w0a[4] = {w0v.x,w0v.y,w0v.z,w0v.w};
    float a0a[4] = {a0v.x,a0v.y,a0v.z,a0v.w};
    float v0a[4] = {v0v.x,v0v.y,v0v.z,v0v.w};

    float aga[4], dec[4], kkpre[4], kmod[4], vb[4];
    float nrm = 0.f;
    #pragma unroll
    for (int c=0;c<4;c++){
        float u = w0a[c] + wtv[c];
        float z = -u;
        float sp = (z > 20.f) ? z : log1pf(expf(z));
        float wraw = -sp - 0.6f;
        dec[c] = expf(-expf(wraw));
        float a = sigmoidf_(a0a[c] + atv[c]);
        aga[c] = a;
        kkpre[c] = kpv[c] * kkwv[c];
        nrm += kkpre[c]*kkpre[c];
        kmod[c] = kpv[c] * (1.f + (a - 1.f) * kawv[c]);
        float vsel = sigmoidf_(v0a[c] + vtv[c]);
        vb[c] = vpv[c] + (vfv[c] - vpv[c]) * vsel;
    }
    float tot = redux16(nrm);
    float inv = 1.f / fmaxf(sqrtf(tot), 1e-12f);

    float aav[4], bbv[4];
    float dsum = 0.f;
    #pragma unroll
    for (int c=0;c<4;c++){
        float kkn = kkpre[c]*inv;
        aav[c] = -kkn;
        bbv[c] = kkn*aga[c];
        dsum += rr[c]*kmod[c]*rkv[c];
    }
    float dtot = redux16(dsum);
    if ((tid & 15) == 0) g_bcoef[(size_t)m*HH + h] = dtot;

    size_t base = ((size_t)(b*HH + h)*TT + t)*384 + (j0 & 63);
    *(float4*)(g_packed + base +   0) = rv;
    *(float4*)(g_packed + base +  64) = make_float4(dec[0],dec[1],dec[2],dec[3]);
    *(float4*)(g_packed + base + 128) = make_float4(kmod[0],kmod[1],kmod[2],kmod[3]);
    *(float4*)(g_packed + base + 192) = make_float4(vb[0],vb[1],vb[2],vb[3]);
    *(float4*)(g_packed + base + 256) = make_float4(aav[0],aav[1],aav[2],aav[3]);
    *(float4*)(g_packed + base + 320) = make_float4(bbv[0],bbv[1],bbv[2],bbv[3]);
}

// ---------------- recurrent scan: one block per (b,h) ----------------
__global__ void __launch_bounds__(256,1) scan_kernel(const float* __restrict__ state0)
{
    __shared__ float buf[4][384];
    __shared__ float redA[64], redB[64];
    const int bh = blockIdx.x;
    const int tid = threadIdx.x;
    const int i = tid >> 2;
    const int q = tid & 3;
    const int kb = q * 16;

    float S[16];
    #pragma unroll
    for (int c=0;c<16;c++)
        S[c] = state0[((size_t)bh*64 + i)*64 + kb + c];

    const float* src = g_packed + (size_t)bh*TT*384;

    if (tid < 96) {
        #pragma unroll
        for (int s=0;s<4;s++){
            cp_async16(&buf[s][tid*4], src + (size_t)s*384 + tid*4);
            asm volatile("cp.async.commit_group;\n");
        }
    }

    const int b = bh >> 5, h = bh & 31;
    float* yout = g_y + ((size_t)b*TT*HH + h)*NNd + i;
    float gsum = 0.f, gsq = 0.f;

    for (int t = 0; t < TT; t++) {
        if (tid < 96) asm volatile("cp.async.wait_group 3;\n");
        __syncthreads();
        const float* vbuf = buf[t & 3];

        float rr[16], dd[16], km[16], av[16], bv[16];
        #pragma unroll
        for (int m4=0;m4<4;m4++){
            float4 x0 = *(const float4*)&vbuf[  0 + kb + m4*4];
            float4 x1 = *(const float4*)&vbuf[ 64 + kb + m4*4];
            float4 x2 = *(const float4*)&vbuf[128 + kb + m4*4];
            float4 x4 = *(const float4*)&vbuf[256 + kb + m4*4];
            float4 x5 = *(const float4*)&vbuf[320 + kb + m4*4];
            rr[m4*4+0]=x0.x; rr[m4*4+1]=x0.y; rr[m4*4+2]=x0.z; rr[m4*4+3]=x0.w;
            dd[m4*4+0]=x1.x; dd[m4*4+1]=x1.y; dd[m4*4+2]=x1.z; dd[m4*4+3]=x1.w;
            km[m4*4+0]=x2.x; km[m4*4+1]=x2.y; km[m4*4+2]=x2.z; km[m4*4+3]=x2.w;
            av[m4*4+0]=x4.x; av[m4*4+1]=x4.y; av[m4*4+2]=x4.z; av[m4*4+3]=x4.w;
            bv[m4*4+0]=x5.x; bv[m4*4+1]=x5.y; bv[m4*4+2]=x5.z; bv[m4*4+3]=x5.w;
        }
        float vi = vbuf[192 + i];

        float sa = 0.f;
        #pragma unroll
        for (int c=0;c<16;c++) sa += S[c]*av[c];
        sa += __shfl_xor_sync(0xffffffffu, sa, 1);
        sa += __shfl_xor_sync(0xffffffffu, sa, 2);

        float yp = 0.f;
        #pragma unroll
        for (int c=0;c<16;c++){
            S[c] = S[c]*dd[c] + sa*bv[c] + vi*km[c];
            yp += S[c]*rr[c];
        }
        yp += __shfl_xor_sync(0xffffffffu, yp, 1);
        yp += __shfl_xor_sync(0xffffffffu, yp, 2);

        if (q == 0) {
            yout[(size_t)t*CC] = yp;
            gsum += yp; gsq += yp*yp;
        }
        __syncthreads();
        if (tid < 96) {
            int tt = (t+4 < TT) ? (t+4) : (TT-1);
            cp_async16(&buf[(t+4)&3][tid*4], src + (size_t)tt*384 + tid*4);
            asm volatile("cp.async.commit_group;\n");
        }
    }

    if (q == 0) { redA[i] = gsum; redB[i] = gsq; }
    __syncthreads();
    if (tid < 32) {
        float s1 = redA[tid] + redA[tid+32];
        float s2 = redB[tid] + redB[tid+32];
        #pragma unroll
        for (int off=16; off>=1; off>>=1){
            s1 += __shfl_xor_sync(0xffffffffu, s1, off);
            s2 += __shfl_xor_sync(0xffffffffu, s2, off);
        }
        if (tid == 0) {
            float cnt = (float)(TT*NNd);
            float mean = s1 / cnt;
            float var  = s2 / cnt - mean*mean;
            g_gn[bh*2]   = mean;
            g_gn[bh*2+1] = rsqrtf(var + 0.00064f);
        }
    }
}

// ---------------- groupnorm apply + bonus, fused fp16 convert ----------------
__global__ void __launch_bounds__(512) apply_kernel(
        const float* __restrict__ ln_w, const float* __restrict__ ln_b)
{
    int m = blockIdx.x;
    int b = m / TT, t = m % TT;
    int tid = threadIdx.x;
    int j0 = tid * 4;
    int h = j0 >> 6;

    float mean = g_gn[(b*HH + h)*2];
    float rstd = g_gn[(b*HH + h)*2 + 1];
    float bc   = g_bcoef[(size_t)m*HH + h];

    float4 yv = *(const float4*)(g_y + (size_t)m*CC + j0);
    float4 lw = *(const float4*)(ln_w + j0);
    float4 lb = *(const float4*)(ln_b + j0);
    size_t pbase = ((size_t)(b*HH + h)*TT + t)*384 + (j0 & 63);
    float4 vb = *(const float4*)(g_packed + pbase + 192);

    float o[4];
    o[0] = (yv.x - mean)*rstd*lw.x + lb.x + bc*vb.x;
    o[1] = (yv.y - mean)*rstd*lw.y + lb.y + bc*vb.y;
    o[2] = (yv.z - mean)*rstd*lw.z + lb.z + bc*vb.z;
    o[3] = (yv.w - mean)*rstd*lw.w + lb.w + bc*vb.w;

    __half hv[4];
    #pragma unroll
    for (int c=0;c<4;c++) hv[c] = __float2half_rn(o[c]);
    *(uint2*)(g_xxh + (size_t)m*CC + j0) = *(uint2*)hv;
}

// ---------------- launch ----------------
extern "C" void kernel_launch(void* const* d_in, const int* in_sizes, int n_in,
                              void* d_out, int out_size)
{
    const float* x      = (const float*)d_in[0];
    const float* vfirst = (const float*)d_in[1];
    const float* state  = (const float*)d_in[2];
    const float* Rw     = (const float*)d_in[3];
    const float* Rb     = (const float*)d_in[4];
    const float* Kw     = (const float*)d_in[5];
    const float* Kb     = (const float*)d_in[6];
    const float* Vw     = (const float*)d_in[7];
    const float* Vb     = (const float*)d_in[8];
    const float* Ow     = (const float*)d_in[9];
    const float* Ob     = (const float*)d_in[10];
    const float* w0     = (const float*)d_in[11];
    const float* w1     = (const float*)d_in[12];
    const float* w2     = (const float*)d_in[13];
    const float* a0     = (const float*)d_in[14];
    const float* a1     = (const float*)d_in[15];
    const float* a2     = (const float*)d_in[16];
    const float* v0     = (const float*)d_in[17];
    const float* v1     = (const float*)d_in[18];
    const float* v2     = (const float*)d_in[19];
    const float* k_k    = (const float*)d_in[20];
    const float* k_a    = (const float*)d_in[21];
    const float* r_k    = (const float*)d_in[22];
    const float* ln_w   = (const float*)d_in[23];
    const float* ln_b   = (const float*)d_in[24];
    float* out = (float*)d_out;

    cudaFuncSetAttribute(hmma_nt, cudaFuncAttributeMaxDynamicSharedMemorySize, NSTAGE*STAGEB);

    float *proj, *wterm, *aterm, *vterm, *bias1;
    __half *xh, *b1hi, *b1lo, *hh;
    __half *w2hi, *w2lo, *a2hi, *a2lo, *v2hi, *v2lo;
    __half *xxh, *ohi, *olo;
    cudaGetSymbolAddress((void**)&proj,  g_proj);
    cudaGetSymbolAddress((void**)&wterm, g_wterm);
    cudaGetSymbolAddress((void**)&aterm, g_aterm);
    cudaGetSymbolAddress((void**)&vterm, g_vterm);
    cudaGetSymbolAddress((void**)&bias1, g_bias1);
    cudaGetSymbolAddress((void**)&xh,    g_xh);
    cudaGetSymbolAddress((void**)&b1hi,  g_b1hi);
    cudaGetSymbolAddress((void**)&b1lo,  g_b1lo);
    cudaGetSymbolAddress((void**)&hh,    g_hidh);
    cudaGetSymbolAddress((void**)&w2hi,  g_w2hi);
    cudaGetSymbolAddress((void**)&w2lo,  g_w2lo);
    cudaGetSymbolAddress((void**)&a2hi,  g_a2hi);
    cudaGetSymbolAddress((void**)&a2lo,  g_a2lo);
    cudaGetSymbolAddress((void**)&v2hi,  g_v2hi);
    cudaGetSymbolAddress((void**)&v2lo,  g_v2lo);
    cudaGetSymbolAddress((void**)&xxh,   g_xxh);
    cudaGetSymbolAddress((void**)&ohi,   g_ohi);
    cudaGetSymbolAddress((void**)&olo,   g_olo);

    // weight packing (hi+lo) + activation convert (hi only)
    pack_b1<<<(int)(((size_t)N1*CC + 255)/256), 256>>>(Rw, Rb, Kw, Kb, Vw, Vb, w1, a1, v1);
    pack_b2<<<(CC*64 + 255)/256, 256>>>(w2, a2, v2);
    split_ox<<<2048, 256>>>(Ow, x);

    // GEMM1: proj = x @ [R|K|V|w1|a1|v1]^T + bias1   (M=4096, N=3328, K=2048)
    {
        dim3 g(N1/128, MM/128);
        hmma_nt<<<g, 256, NSTAGE*STAGEB>>>(xh, CC, b1hi, b1lo, CC, bias1, proj, N1, CC/32);
    }
    hid_cvt<<<(int)(((size_t)MM*HIDP + 255)/256), 256>>>();

    // stage-2 small-K GEMMs (K=64 -> KT=2)
    {
        dim3 g(CC/128, MM/128);
        hmma_nt<<<g, 256, NSTAGE*STAGEB>>>(hh,       HIDP, w2hi, w2lo, 64, nullptr, wterm, CC, 2);
        hmma_nt<<<g, 256, NSTAGE*STAGEB>>>(hh + 64,  HIDP, a2hi, a2lo, 64, nullptr, aterm, CC, 2);
        hmma_nt<<<g, 256, NSTAGE*STAGEB>>>(hh + 128, HIDP, v2hi, v2lo, 64, nullptr, vterm, CC, 2);
    }

    prep_kernel<<<MM, 512>>>(vfirst, w0, a0, v0, k_k, k_a, r_k);
    scan_kernel<<<BB*HH, 256>>>(state);
    apply_kernel<<<MM, 512>>>(ln_w, ln_b);

    // out = xx @ O^T + O_bias   (M=4096, N=2048, K=2048)
    {
        dim3 g(CC/128, MM/128);
        hmma_nt<<<g, 256, NSTAGE*STAGEB>>>(xxh, CC, ohi, olo, CC, Ob, out, CC, CC/32);
    }
}